// round 1
// baseline (speedup 1.0000x reference)
#include <cuda_runtime.h>
#include <cuda_bf16.h>

#define NN 50000
#define RR 8
#define HH 128
#define CC 40
#define EE 800000

// ---- scratch (device globals; no allocation allowed) ----
__device__ float g_cnt[NN * RR];                       // 1.6 MB: counts -> inverted weights
__device__ float g_h[(size_t)NN * HH];                 // 25.6 MB: layer-1 output
__device__ float g_xr[(size_t)RR * NN * HH];           // 204.8 MB: xr[r] = h @ W2[r]
__device__ float g_h2[(size_t)NN * HH];                // 25.6 MB: layer-2 pre-relu

// ------------------------------------------------------------------
// zero g_h and g_cnt (needed fresh every graph replay)
// ------------------------------------------------------------------
__global__ void zero_kernel() {
    size_t tid = (size_t)blockIdx.x * blockDim.x + threadIdx.x;
    size_t stride = (size_t)gridDim.x * blockDim.x;
    float4 z = make_float4(0.f, 0.f, 0.f, 0.f);
    float4* h4 = reinterpret_cast<float4*>(g_h);
    for (size_t i = tid; i < (size_t)NN * HH / 4; i += stride) h4[i] = z;
    float4* c4 = reinterpret_cast<float4*>(g_cnt);
    for (size_t i = tid; i < (size_t)NN * RR / 4; i += stride) c4[i] = z;
}

// ------------------------------------------------------------------
// per (dst, relation) edge counts
// ------------------------------------------------------------------
__global__ void count_kernel(const int* __restrict__ ei, const int* __restrict__ et) {
    int e = blockIdx.x * blockDim.x + threadIdx.x;
    if (e < EE) {
        int dst = ei[EE + e];
        int r = et[e];
        atomicAdd(&g_cnt[dst * RR + r], 1.0f);
    }
}

__global__ void invert_kernel() {
    int i = blockIdx.x * blockDim.x + threadIdx.x;
    if (i < NN * RR) g_cnt[i] = 1.0f / fmaxf(g_cnt[i], 1.0f);
}

// ------------------------------------------------------------------
// layer 1 scatter: h[dst] += w * W1[et, src]   (one warp per edge)
// ------------------------------------------------------------------
__global__ void scatter1_kernel(const int* __restrict__ ei, const int* __restrict__ et,
                                const float* __restrict__ W1) {
    int warp = (blockIdx.x * blockDim.x + threadIdx.x) >> 5;
    int lane = threadIdx.x & 31;
    if (warp >= EE) return;
    int src = ei[warp];
    int dst = ei[EE + warp];
    int r = et[warp];
    float w = g_cnt[dst * RR + r];  // already inverted
    float4 v = reinterpret_cast<const float4*>(W1)[((size_t)r * NN + src) * (HH / 4) + lane];
    float* o = g_h + (size_t)dst * HH + lane * 4;
    atomicAdd(o + 0, w * v.x);
    atomicAdd(o + 1, w * v.y);
    atomicAdd(o + 2, w * v.z);
    atomicAdd(o + 3, w * v.w);
}

// ------------------------------------------------------------------
// h = relu(h + root1 + b1)
// ------------------------------------------------------------------
__global__ void finalize1_kernel(const float* __restrict__ root1, const float* __restrict__ b1) {
    int i = blockIdx.x * blockDim.x + threadIdx.x;
    if (i < NN * HH / 4) {
        float4 h = reinterpret_cast<float4*>(g_h)[i];
        float4 r = reinterpret_cast<const float4*>(root1)[i];
        float4 b = reinterpret_cast<const float4*>(b1)[i & (HH / 4 - 1)];
        h.x = fmaxf(h.x + r.x + b.x, 0.f);
        h.y = fmaxf(h.y + r.y + b.y, 0.f);
        h.z = fmaxf(h.z + r.z + b.z, 0.f);
        h.w = fmaxf(h.w + r.w + b.w, 0.f);
        reinterpret_cast<float4*>(g_h)[i] = h;
    }
}

// ------------------------------------------------------------------
// 9 GEMMs: z<8: g_xr[z] = h @ W2[z] ; z==8: g_h2 = h @ root2 + b2
// classic SIMT sgemm: BM=128, BN=128, BK=8, 256 threads, 8x8 per thread
// ------------------------------------------------------------------
__global__ __launch_bounds__(256, 2) void gemm_kernel(const float* __restrict__ W2,
                                                      const float* __restrict__ root2,
                                                      const float* __restrict__ b2) {
    const int z = blockIdx.z;
    const float* __restrict__ B = (z < RR) ? (W2 + (size_t)z * HH * HH) : root2;
    float* out = (z < RR) ? (g_xr + (size_t)z * NN * HH) : g_h2;
    const int row0 = blockIdx.x * 128;

    __shared__ float As[8][128];
    __shared__ float Bs[8][128];

    const int tid = threadIdx.x;
    const int arow = tid >> 1;          // 0..127
    const int acol = (tid & 1) * 4;     // 0 or 4
    const int brow = tid >> 5;          // 0..7
    const int bcol = (tid & 31) * 4;    // 0..124
    const int tx = tid & 15;
    const int ty = tid >> 4;

    float acc[8][8];
#pragma unroll
    for (int i = 0; i < 8; i++)
#pragma unroll
        for (int j = 0; j < 8; j++) acc[i][j] = 0.f;

    const int gr = row0 + arow;
    const bool avalid = gr < NN;
    const float* aptr = g_h + (size_t)(avalid ? gr : 0) * HH + acol;

    for (int k0 = 0; k0 < HH; k0 += 8) {
        float4 av = make_float4(0.f, 0.f, 0.f, 0.f);
        if (avalid) av = *reinterpret_cast<const float4*>(aptr + k0);
        As[acol + 0][arow] = av.x;
        As[acol + 1][arow] = av.y;
        As[acol + 2][arow] = av.z;
        As[acol + 3][arow] = av.w;
        *reinterpret_cast<float4*>(&Bs[brow][bcol]) =
            *reinterpret_cast<const float4*>(B + (size_t)(k0 + brow) * HH + bcol);
        __syncthreads();
#pragma unroll
        for (int k = 0; k < 8; k++) {
            float a[8], b[8];
            *reinterpret_cast<float4*>(&a[0]) = *reinterpret_cast<const float4*>(&As[k][ty * 8]);
            *reinterpret_cast<float4*>(&a[4]) = *reinterpret_cast<const float4*>(&As[k][ty * 8 + 4]);
            *reinterpret_cast<float4*>(&b[0]) = *reinterpret_cast<const float4*>(&Bs[k][tx * 8]);
            *reinterpret_cast<float4*>(&b[4]) = *reinterpret_cast<const float4*>(&Bs[k][tx * 8 + 4]);
#pragma unroll
            for (int i = 0; i < 8; i++)
#pragma unroll
                for (int j = 0; j < 8; j++) acc[i][j] = fmaf(a[i], b[j], acc[i][j]);
        }
        __syncthreads();
    }

    float bias[8];
#pragma unroll
    for (int j = 0; j < 8; j++) bias[j] = (z == RR) ? b2[tx * 8 + j] : 0.f;

#pragma unroll
    for (int i = 0; i < 8; i++) {
        int r = row0 + ty * 8 + i;
        if (r < NN) {
            float4 v0 = make_float4(acc[i][0] + bias[0], acc[i][1] + bias[1],
                                    acc[i][2] + bias[2], acc[i][3] + bias[3]);
            float4 v1 = make_float4(acc[i][4] + bias[4], acc[i][5] + bias[5],
                                    acc[i][6] + bias[6], acc[i][7] + bias[7]);
            *reinterpret_cast<float4*>(out + (size_t)r * HH + tx * 8) = v0;
            *reinterpret_cast<float4*>(out + (size_t)r * HH + tx * 8 + 4) = v1;
        }
    }
}

// ------------------------------------------------------------------
// layer 2 scatter: h2[dst] += w * xr[et, src]   (one warp per edge)
// (g_h2 already holds h @ root2 + b2 from gemm z==8)
// ------------------------------------------------------------------
__global__ void scatter2_kernel(const int* __restrict__ ei, const int* __restrict__ et) {
    int warp = (blockIdx.x * blockDim.x + threadIdx.x) >> 5;
    int lane = threadIdx.x & 31;
    if (warp >= EE) return;
    int src = ei[warp];
    int dst = ei[EE + warp];
    int r = et[warp];
    float w = g_cnt[dst * RR + r];
    float4 v = reinterpret_cast<const float4*>(g_xr)[((size_t)r * NN + src) * (HH / 4) + lane];
    float* o = g_h2 + (size_t)dst * HH + lane * 4;
    atomicAdd(o + 0, w * v.x);
    atomicAdd(o + 1, w * v.y);
    atomicAdd(o + 2, w * v.z);
    atomicAdd(o + 3, w * v.w);
}

// ------------------------------------------------------------------
// out = relu(h2) @ lin_w + lin_b    (32 nodes per block)
// ------------------------------------------------------------------
__global__ void final_kernel(const float* __restrict__ lin_w, const float* __restrict__ lin_b,
                             float* __restrict__ out) {
    __shared__ float sw[HH * CC];      // 20 KB
    __shared__ float sh[32][HH + 1];   // 16.5 KB
    int tid = threadIdx.x;
    for (int i = tid; i < HH * CC; i += 256) sw[i] = lin_w[i];
    int n0 = blockIdx.x * 32;
    for (int i = tid; i < 32 * HH; i += 256) {
        int nl = i / HH, k = i % HH;
        int n = n0 + nl;
        sh[nl][k] = (n < NN) ? fmaxf(g_h2[(size_t)n * HH + k], 0.f) : 0.f;
    }
    __syncthreads();
#pragma unroll
    for (int j = 0; j < 5; j++) {
        int idx = tid + j * 256;       // 0..1279 covers 32*40
        int nl = idx / CC, c = idx % CC;
        float acc = lin_b[c];
#pragma unroll
        for (int k = 0; k < HH; k++) acc = fmaf(sh[nl][k], sw[k * CC + c], acc);
        int n = n0 + nl;
        if (n < NN) out[(size_t)n * CC + c] = acc;
    }
}

// ------------------------------------------------------------------
extern "C" void kernel_launch(void* const* d_in, const int* in_sizes, int n_in,
                              void* d_out, int out_size) {
    const int* ei = (const int*)d_in[0];      // [2, E]
    const int* et = (const int*)d_in[1];      // [E]
    const float* W1 = (const float*)d_in[2];  // [R, N, H]
    const float* root1 = (const float*)d_in[3];
    const float* b1 = (const float*)d_in[4];
    const float* W2 = (const float*)d_in[5];  // [R, H, H]
    const float* root2 = (const float*)d_in[6];
    const float* b2 = (const float*)d_in[7];
    const float* lin_w = (const float*)d_in[8];
    const float* lin_b = (const float*)d_in[9];
    float* out = (float*)d_out;

    zero_kernel<<<2048, 256>>>();
    count_kernel<<<(EE + 255) / 256, 256>>>(ei, et);
    invert_kernel<<<(NN * RR + 255) / 256, 256>>>();
    scatter1_kernel<<<(EE * 32) / 256, 256>>>(ei, et, W1);
    finalize1_kernel<<<(NN * HH / 4 + 255) / 256, 256>>>(root1, b1);
    dim3 ggrid((NN + 127) / 128, 1, RR + 1);
    gemm_kernel<<<ggrid, 256>>>(W2, root2, b2);
    scatter2_kernel<<<(EE * 32) / 256, 256>>>(ei, et);
    final_kernel<<<(NN + 31) / 32, 256>>>(lin_w, lin_b, out);
}

// round 6
// speedup vs baseline: 1.7913x; 1.7913x over previous
#include <cuda_runtime.h>
#include <cuda_bf16.h>
#include <cstdint>

#define NN 50000
#define RR 8
#define HH 128
#define CC 40
#define EE 800000
#define NZ 9           // 8 relations + root2
#define MTILES 391     // ceil(NN/128)

// ---- scratch (device globals; no allocation allowed) ----
__device__ float g_cnt[NN * RR];
__device__ float g_h[(size_t)NN * HH];
__device__ float g_xr[(size_t)RR * NN * HH];
__device__ float g_h2[(size_t)NN * HH];
__device__ __nv_bfloat16 g_Ahi[(size_t)NN * HH];
__device__ __nv_bfloat16 g_Alo[(size_t)NN * HH];
__device__ __nv_bfloat16 g_Bhi[(size_t)NZ * HH * HH];   // transposed: [z][n][k]
__device__ __nv_bfloat16 g_Blo[(size_t)NZ * HH * HH];

// ================= PTX helpers =================
__device__ __forceinline__ uint32_t smem_u32(const void* p) {
    uint32_t a;
    asm("{ .reg .u64 t; cvta.to.shared.u64 t, %1; cvt.u32.u64 %0, t; }" : "=r"(a) : "l"(p));
    return a;
}
__device__ __forceinline__ void red4(float* p, float x, float y, float z, float w) {
    asm volatile("red.global.add.v4.f32 [%0], {%1,%2,%3,%4};"
                 :: "l"(p), "f"(x), "f"(y), "f"(z), "f"(w) : "memory");
}
__device__ __forceinline__ void ldsm4(uint32_t* r, uint32_t addr) {
    asm volatile("ldmatrix.sync.aligned.m8n8.x4.shared.b16 {%0,%1,%2,%3}, [%4];"
                 : "=r"(r[0]), "=r"(r[1]), "=r"(r[2]), "=r"(r[3]) : "r"(addr));
}
__device__ __forceinline__ void mma_bf16(float* d, const uint32_t* a, const uint32_t* b) {
    asm volatile(
        "mma.sync.aligned.m16n8k16.row.col.f32.bf16.bf16.f32 "
        "{%0,%1,%2,%3}, {%4,%5,%6,%7}, {%8,%9}, {%0,%1,%2,%3};"
        : "+f"(d[0]), "+f"(d[1]), "+f"(d[2]), "+f"(d[3])
        : "r"(a[0]), "r"(a[1]), "r"(a[2]), "r"(a[3]), "r"(b[0]), "r"(b[1]));
}

// ================= phase kernels =================
__global__ void zero_kernel() {
    size_t tid = (size_t)blockIdx.x * blockDim.x + threadIdx.x;
    size_t stride = (size_t)gridDim.x * blockDim.x;
    float4 z = make_float4(0.f, 0.f, 0.f, 0.f);
    float4* h4 = reinterpret_cast<float4*>(g_h);
    for (size_t i = tid; i < (size_t)NN * HH / 4; i += stride) h4[i] = z;
    float4* c4 = reinterpret_cast<float4*>(g_cnt);
    for (size_t i = tid; i < (size_t)NN * RR / 4; i += stride) c4[i] = z;
}

__global__ void count_kernel(const int* __restrict__ ei, const int* __restrict__ et) {
    int e = blockIdx.x * blockDim.x + threadIdx.x;
    if (e < EE) atomicAdd(&g_cnt[ei[EE + e] * RR + et[e]], 1.0f);
}

__global__ void invert_kernel() {
    int i = blockIdx.x * blockDim.x + threadIdx.x;
    if (i < NN * RR) g_cnt[i] = 1.0f / fmaxf(g_cnt[i], 1.0f);
}

// layer 1 scatter: h[dst] += w * W1[et, src]   (warp per edge, vector RED)
__global__ void scatter1_kernel(const int* __restrict__ ei, const int* __restrict__ et,
                                const float* __restrict__ W1) {
    int warp = (blockIdx.x * blockDim.x + threadIdx.x) >> 5;
    int lane = threadIdx.x & 31;
    if (warp >= EE) return;
    int src = ei[warp];
    int dst = ei[EE + warp];
    int r = et[warp];
    float w = g_cnt[dst * RR + r];
    float4 v = reinterpret_cast<const float4*>(W1)[((size_t)r * NN + src) * (HH / 4) + lane];
    red4(g_h + (size_t)dst * HH + lane * 4, w * v.x, w * v.y, w * v.z, w * v.w);
}

__global__ void finalize1_kernel(const float* __restrict__ root1, const float* __restrict__ b1) {
    int i = blockIdx.x * blockDim.x + threadIdx.x;
    if (i < NN * HH / 4) {
        float4 h = reinterpret_cast<float4*>(g_h)[i];
        float4 r = reinterpret_cast<const float4*>(root1)[i];
        float4 b = reinterpret_cast<const float4*>(b1)[i & (HH / 4 - 1)];
        h.x = fmaxf(h.x + r.x + b.x, 0.f);
        h.y = fmaxf(h.y + r.y + b.y, 0.f);
        h.z = fmaxf(h.z + r.z + b.z, 0.f);
        h.w = fmaxf(h.w + r.w + b.w, 0.f);
        reinterpret_cast<float4*>(g_h)[i] = h;
    }
}

// h -> bf16 hi/lo split
__global__ void prepA_kernel() {
    int i = blockIdx.x * blockDim.x + threadIdx.x;
    if (i >= NN * HH / 4) return;
    float4 v = reinterpret_cast<const float4*>(g_h)[i];
    __nv_bfloat16 hx = __float2bfloat16(v.x), hy = __float2bfloat16(v.y);
    __nv_bfloat16 hz = __float2bfloat16(v.z), hw = __float2bfloat16(v.w);
    __nv_bfloat16 lx = __float2bfloat16(v.x - __bfloat162float(hx));
    __nv_bfloat16 ly = __float2bfloat16(v.y - __bfloat162float(hy));
    __nv_bfloat16 lz = __float2bfloat16(v.z - __bfloat162float(hz));
    __nv_bfloat16 lw = __float2bfloat16(v.w - __bfloat162float(hw));
    __nv_bfloat162 h0 = __halves2bfloat162(hx, hy), h1 = __halves2bfloat162(hz, hw);
    __nv_bfloat162 l0 = __halves2bfloat162(lx, ly), l1 = __halves2bfloat162(lz, lw);
    uint2 ph, pl;
    ph.x = *reinterpret_cast<uint32_t*>(&h0); ph.y = *reinterpret_cast<uint32_t*>(&h1);
    pl.x = *reinterpret_cast<uint32_t*>(&l0); pl.y = *reinterpret_cast<uint32_t*>(&l1);
    reinterpret_cast<uint2*>(g_Ahi)[i] = ph;
    reinterpret_cast<uint2*>(g_Alo)[i] = pl;
}

// W2 / root2 -> transposed bf16 hi/lo:  B[z][n][k] = W[z][k][n]
__global__ void prepB_kernel(const float* __restrict__ W2, const float* __restrict__ root2) {
    int idx = blockIdx.x * blockDim.x + threadIdx.x;
    if (idx >= NZ * HH * HH) return;
    int z = idx >> 14;
    int n = (idx >> 7) & 127;
    int k = idx & 127;
    float v = (z < RR) ? W2[((size_t)z << 14) + k * HH + n] : root2[k * HH + n];
    __nv_bfloat16 hi = __float2bfloat16(v);
    __nv_bfloat16 lo = __float2bfloat16(v - __bfloat162float(hi));
    g_Bhi[idx] = hi;
    g_Blo[idx] = lo;
}

// ================= HMMA GEMM =================
// one CTA per 128-row tile; loops z=0..8; D = Ahi*Bhi + Ahi*Blo + Alo*Bhi
// 256 threads = 8 warps; warp tile 32(M) x 64(N); full K=128 staged in smem.
#define PITCH 136                       // bf16 elements per smem row (pad 8)
#define PITCHB (PITCH * 2)              // bytes
static constexpr int SM_AHI = 0;
static constexpr int SM_ALO = SM_AHI + 128 * PITCHB;
static constexpr int SM_BHI = SM_ALO + 128 * PITCHB;
static constexpr int SM_BLO = SM_BHI + 128 * PITCHB;
static constexpr int SM_TOTAL = SM_BLO + 128 * PITCHB;   // 139264 B

__global__ __launch_bounds__(256, 1) void gemm_kernel(const float* __restrict__ b2) {
    extern __shared__ char smem[];
    uint32_t sb = smem_u32(smem);
    const int tid = threadIdx.x;
    const int wid = tid >> 5, lane = tid & 31;
    const int warp_m = (wid & 3) * 32;         // 0,32,64,96
    const int warp_n = (wid >> 2) * 64;        // 0,64
    const int row0 = blockIdx.x * 128;

    // ---- stage A hi/lo (once): 128 rows x 128 bf16, each thread 8 uint4 segs
    {
        uint4 zz = make_uint4(0, 0, 0, 0);
#pragma unroll
        for (int i = 0; i < 8; i++) {
            int idx = tid + i * 256;           // 0..2047
            int row = idx >> 4, seg = idx & 15;
            int gr = row0 + row;
            bool v = gr < NN;
            uint32_t so = row * PITCHB + seg * 16;
            const uint4* Ah = reinterpret_cast<const uint4*>(g_Ahi) + (size_t)gr * 16 + seg;
            const uint4* Al = reinterpret_cast<const uint4*>(g_Alo) + (size_t)gr * 16 + seg;
            *reinterpret_cast<uint4*>(smem + SM_AHI + so) = v ? *Ah : zz;
            *reinterpret_cast<uint4*>(smem + SM_ALO + so) = v ? *Al : zz;
        }
    }

    // precomputed fragment smem addresses (byte offsets within a tile)
    // A: row = warp_m + mt*16 + (lane&15), col = k*16 + (lane>>4)*8
    const uint32_t a_row = (uint32_t)(warp_m + (lane & 15));
    const uint32_t a_base = a_row * PITCHB + ((lane >> 4) << 3) * 2;
    // B: n = warp_n + ntp*16 + (lane&7) + ((lane>>4)<<3), col = k*16 + (((lane>>3)&1)<<3)
    const uint32_t b_n = (uint32_t)(warp_n + (lane & 7) + ((lane >> 4) << 3));
    const uint32_t b_base = b_n * PITCHB + (((lane >> 3) & 1) << 3) * 2;

    for (int z = 0; z < NZ; z++) {
        __syncthreads();   // previous iteration's mma reads of B done
        // ---- stage B hi/lo for this z (z-stride = 2048 uint4 = 16384 bf16)
#pragma unroll
        for (int i = 0; i < 8; i++) {
            int idx = tid + i * 256;
            int row = idx >> 4, seg = idx & 15;
            uint32_t so = row * PITCHB + seg * 16;
            const uint4* Bh = reinterpret_cast<const uint4*>(g_Bhi) + (size_t)z * 2048 + row * 16 + seg;
            const uint4* Bl = reinterpret_cast<const uint4*>(g_Blo) + (size_t)z * 2048 + row * 16 + seg;
            *reinterpret_cast<uint4*>(smem + SM_BHI + so) = *Bh;
            *reinterpret_cast<uint4*>(smem + SM_BLO + so) = *Bl;
        }
        __syncthreads();

        float acc[16][4];   // [mt*8+nt][4]
#pragma unroll
        for (int i = 0; i < 16; i++)
#pragma unroll
            for (int j = 0; j < 4; j++) acc[i][j] = 0.f;

#pragma unroll
        for (int k = 0; k < 8; k++) {
            const uint32_t koff = (uint32_t)(k * 32);   // k*16 elements * 2B
            uint32_t ahi[2][4], alo[2][4];
#pragma unroll
            for (int mt = 0; mt < 2; mt++) {
                uint32_t ao = a_base + (uint32_t)(mt * 16) * PITCHB + koff;
                ldsm4(ahi[mt], sb + SM_AHI + ao);
                ldsm4(alo[mt], sb + SM_ALO + ao);
            }
            uint32_t bhi[8][2], blo[8][2];
#pragma unroll
            for (int ntp = 0; ntp < 4; ntp++) {
                uint32_t bo = b_base + (uint32_t)(ntp * 16) * PITCHB + koff;
                uint32_t rh[4], rl[4];
                ldsm4(rh, sb + SM_BHI + bo);
                ldsm4(rl, sb + SM_BLO + bo);
                bhi[ntp * 2][0] = rh[0]; bhi[ntp * 2][1] = rh[1];
                bhi[ntp * 2 + 1][0] = rh[2]; bhi[ntp * 2 + 1][1] = rh[3];
                blo[ntp * 2][0] = rl[0]; blo[ntp * 2][1] = rl[1];
                blo[ntp * 2 + 1][0] = rl[2]; blo[ntp * 2 + 1][1] = rl[3];
            }
#pragma unroll
            for (int mt = 0; mt < 2; mt++)
#pragma unroll
                for (int nt = 0; nt < 8; nt++) {
                    mma_bf16(acc[mt * 8 + nt], ahi[mt], bhi[nt]);
                    mma_bf16(acc[mt * 8 + nt], ahi[mt], blo[nt]);
                    mma_bf16(acc[mt * 8 + nt], alo[mt], bhi[nt]);
                }
        }

        // ---- epilogue
        float* out = (z < RR) ? (g_xr + (size_t)z * NN * HH) : g_h2;
        const int erow = lane >> 2;
        const int ecol0 = (lane & 3) * 2;
#pragma unroll
        for (int mt = 0; mt < 2; mt++) {
            int r0 = row0 + warp_m + mt * 16 + erow;
            int r1 = r0 + 8;
            bool v0 = r0 < NN, v1 = r1 < NN;
#pragma unroll
            for (int nt = 0; nt < 8; nt++) {
                int c = warp_n + nt * 8 + ecol0;
                float bb0 = 0.f, bb1 = 0.f;
                if (z == RR) { bb0 = b2[c]; bb1 = b2[c + 1]; }
                float* acc4 = acc[mt * 8 + nt];
                if (v0) {
                    float2 o = make_float2(acc4[0] + bb0, acc4[1] + bb1);
                    *reinterpret_cast<float2*>(out + (size_t)r0 * HH + c) = o;
                }
                if (v1) {
                    float2 o = make_float2(acc4[2] + bb0, acc4[3] + bb1);
                    *reinterpret_cast<float2*>(out + (size_t)r1 * HH + c) = o;
                }
            }
        }
    }
}

// layer 2 scatter: h2[dst] += w * xr[et, src]   (warp per edge, vector RED)
__global__ void scatter2_kernel(const int* __restrict__ ei, const int* __restrict__ et) {
    int warp = (blockIdx.x * blockDim.x + threadIdx.x) >> 5;
    int lane = threadIdx.x & 31;
    if (warp >= EE) return;
    int src = ei[warp];
    int dst = ei[EE + warp];
    int r = et[warp];
    float w = g_cnt[dst * RR + r];
    float4 v = reinterpret_cast<const float4*>(g_xr)[((size_t)r * NN + src) * (HH / 4) + lane];
    red4(g_h2 + (size_t)dst * HH + lane * 4, w * v.x, w * v.y, w * v.z, w * v.w);
}

// out = relu(h2) @ lin_w + lin_b
__global__ void final_kernel(const float* __restrict__ lin_w, const float* __restrict__ lin_b,
                             float* __restrict__ out) {
    __shared__ float sw[HH * CC];
    __shared__ float sh[32][HH + 1];
    int tid = threadIdx.x;
    for (int i = tid; i < HH * CC; i += 256) sw[i] = lin_w[i];
    int n0 = blockIdx.x * 32;
    for (int i = tid; i < 32 * HH; i += 256) {
        int nl = i / HH, k = i % HH;
        int n = n0 + nl;
        sh[nl][k] = (n < NN) ? fmaxf(g_h2[(size_t)n * HH + k], 0.f) : 0.f;
    }
    __syncthreads();
#pragma unroll
    for (int j = 0; j < 5; j++) {
        int idx = tid + j * 256;
        int nl = idx / CC, c = idx % CC;
        float acc = lin_b[c];
#pragma unroll
        for (int k = 0; k < HH; k++) acc = fmaf(sh[nl][k], sw[k * CC + c], acc);
        int n = n0 + nl;
        if (n < NN) out[(size_t)n * CC + c] = acc;
    }
}

// ================= launch =================
extern "C" void kernel_launch(void* const* d_in, const int* in_sizes, int n_in,
                              void* d_out, int out_size) {
    const int* ei = (const int*)d_in[0];
    const int* et = (const int*)d_in[1];
    const float* W1 = (const float*)d_in[2];
    const float* root1 = (const float*)d_in[3];
    const float* b1 = (const float*)d_in[4];
    const float* W2 = (const float*)d_in[5];
    const float* root2 = (const float*)d_in[6];
    const float* b2 = (const float*)d_in[7];
    const float* lin_w = (const float*)d_in[8];
    const float* lin_b = (const float*)d_in[9];
    float* out = (float*)d_out;

    cudaFuncSetAttribute(gemm_kernel, cudaFuncAttributeMaxDynamicSharedMemorySize, SM_TOTAL);

    zero_kernel<<<2048, 256>>>();
    prepB_kernel<<<(NZ * HH * HH + 255) / 256, 256>>>(W2, root2);
    count_kernel<<<(EE + 255) / 256, 256>>>(ei, et);
    invert_kernel<<<(NN * RR + 255) / 256, 256>>>();
    scatter1_kernel<<<(EE * 32) / 256, 256>>>(ei, et, W1);
    finalize1_kernel<<<(NN * HH / 4 + 255) / 256, 256>>>(root1, b1);
    prepA_kernel<<<(NN * HH / 4 + 255) / 256, 256>>>();
    gemm_kernel<<<MTILES, 256, SM_TOTAL>>>(b2);
    scatter2_kernel<<<(EE * 32) / 256, 256>>>(ei, et);
    final_kernel<<<(NN + 31) / 32, 256>>>(lin_w, lin_b, out);
}

// round 7
// speedup vs baseline: 1.9160x; 1.0696x over previous
#include <cuda_runtime.h>
#include <cuda_bf16.h>
#include <cuda_fp16.h>
#include <cstdint>

#define NN 50000
#define RR 8
#define HH 128
#define CC 40
#define EE 800000
#define NZ 9           // 8 relations + root2
#define MTILES 391     // ceil(NN/128)

// ---- scratch (device globals; no allocation allowed) ----
__device__ float g_cnt[NN * RR];
__device__ float g_h[(size_t)NN * HH];                 // layer-1 fp32 accumulator
__device__ __half g_xr[(size_t)RR * NN * HH];          // 102.4 MB: xr in fp16
__device__ float g_h2[(size_t)NN * HH];
__device__ __nv_bfloat16 g_Ahi[(size_t)NN * HH];
__device__ __nv_bfloat16 g_Alo[(size_t)NN * HH];
__device__ __nv_bfloat16 g_Bhi[(size_t)NZ * HH * HH];  // transposed: [z][n][k]
__device__ __nv_bfloat16 g_Blo[(size_t)NZ * HH * HH];

// ================= PTX helpers =================
__device__ __forceinline__ uint32_t smem_u32(const void* p) {
    uint32_t a;
    asm("{ .reg .u64 t; cvta.to.shared.u64 t, %1; cvt.u32.u64 %0, t; }" : "=r"(a) : "l"(p));
    return a;
}
__device__ __forceinline__ void red4(float* p, float x, float y, float z, float w) {
    asm volatile("red.global.add.v4.f32 [%0], {%1,%2,%3,%4};"
                 :: "l"(p), "f"(x), "f"(y), "f"(z), "f"(w) : "memory");
}
__device__ __forceinline__ void ldsm4(uint32_t* r, uint32_t addr) {
    asm volatile("ldmatrix.sync.aligned.m8n8.x4.shared.b16 {%0,%1,%2,%3}, [%4];"
                 : "=r"(r[0]), "=r"(r[1]), "=r"(r[2]), "=r"(r[3]) : "r"(addr));
}
__device__ __forceinline__ void mma_bf16(float* d, const uint32_t* a, const uint32_t* b) {
    asm volatile(
        "mma.sync.aligned.m16n8k16.row.col.f32.bf16.bf16.f32 "
        "{%0,%1,%2,%3}, {%4,%5,%6,%7}, {%8,%9}, {%0,%1,%2,%3};"
        : "+f"(d[0]), "+f"(d[1]), "+f"(d[2]), "+f"(d[3])
        : "r"(a[0]), "r"(a[1]), "r"(a[2]), "r"(a[3]), "r"(b[0]), "r"(b[1]));
}

// ================= phase kernels =================
__global__ void zero_kernel() {
    size_t tid = (size_t)blockIdx.x * blockDim.x + threadIdx.x;
    size_t stride = (size_t)gridDim.x * blockDim.x;
    float4 z = make_float4(0.f, 0.f, 0.f, 0.f);
    float4* h4 = reinterpret_cast<float4*>(g_h);
    for (size_t i = tid; i < (size_t)NN * HH / 4; i += stride) h4[i] = z;
    float4* c4 = reinterpret_cast<float4*>(g_cnt);
    for (size_t i = tid; i < (size_t)NN * RR / 4; i += stride) c4[i] = z;
}

__global__ void count_kernel(const int* __restrict__ ei, const int* __restrict__ et) {
    int e = blockIdx.x * blockDim.x + threadIdx.x;
    if (e < EE) atomicAdd(&g_cnt[ei[EE + e] * RR + et[e]], 1.0f);
}

__global__ void invert_kernel() {
    int i = blockIdx.x * blockDim.x + threadIdx.x;
    if (i < NN * RR) g_cnt[i] = 1.0f / fmaxf(g_cnt[i], 1.0f);
}

// layer 1 scatter: h[dst] += w * W1[et, src]   (warp per edge, vector RED)
__global__ void scatter1_kernel(const int* __restrict__ ei, const int* __restrict__ et,
                                const float* __restrict__ W1) {
    int warp = (blockIdx.x * blockDim.x + threadIdx.x) >> 5;
    int lane = threadIdx.x & 31;
    if (warp >= EE) return;
    int src = ei[warp];
    int dst = ei[EE + warp];
    int r = et[warp];
    float w = g_cnt[dst * RR + r];
    float4 v = reinterpret_cast<const float4*>(W1)[((size_t)r * NN + src) * (HH / 4) + lane];
    red4(g_h + (size_t)dst * HH + lane * 4, w * v.x, w * v.y, w * v.z, w * v.w);
}

// fused: h = relu(g_h + root1 + b1) -> bf16 hi/lo split (g_h fp32 never re-written)
__global__ void fin1prepA_kernel(const float* __restrict__ root1, const float* __restrict__ b1) {
    int i = blockIdx.x * blockDim.x + threadIdx.x;
    if (i >= NN * HH / 4) return;
    float4 h = reinterpret_cast<const float4*>(g_h)[i];
    float4 r = reinterpret_cast<const float4*>(root1)[i];
    float4 b = reinterpret_cast<const float4*>(b1)[i & (HH / 4 - 1)];
    float x = fmaxf(h.x + r.x + b.x, 0.f);
    float y = fmaxf(h.y + r.y + b.y, 0.f);
    float z = fmaxf(h.z + r.z + b.z, 0.f);
    float w = fmaxf(h.w + r.w + b.w, 0.f);
    __nv_bfloat16 hx = __float2bfloat16(x), hy = __float2bfloat16(y);
    __nv_bfloat16 hz = __float2bfloat16(z), hw = __float2bfloat16(w);
    __nv_bfloat16 lx = __float2bfloat16(x - __bfloat162float(hx));
    __nv_bfloat16 ly = __float2bfloat16(y - __bfloat162float(hy));
    __nv_bfloat16 lz = __float2bfloat16(z - __bfloat162float(hz));
    __nv_bfloat16 lw = __float2bfloat16(w - __bfloat162float(hw));
    __nv_bfloat162 h0 = __halves2bfloat162(hx, hy), h1 = __halves2bfloat162(hz, hw);
    __nv_bfloat162 l0 = __halves2bfloat162(lx, ly), l1 = __halves2bfloat162(lz, lw);
    uint2 ph, pl;
    ph.x = *reinterpret_cast<uint32_t*>(&h0); ph.y = *reinterpret_cast<uint32_t*>(&h1);
    pl.x = *reinterpret_cast<uint32_t*>(&l0); pl.y = *reinterpret_cast<uint32_t*>(&l1);
    reinterpret_cast<uint2*>(g_Ahi)[i] = ph;
    reinterpret_cast<uint2*>(g_Alo)[i] = pl;
}

// W2 / root2 -> transposed bf16 hi/lo:  B[z][n][k] = W[z][k][n]
__global__ void prepB_kernel(const float* __restrict__ W2, const float* __restrict__ root2) {
    int idx = blockIdx.x * blockDim.x + threadIdx.x;
    if (idx >= NZ * HH * HH) return;
    int z = idx >> 14;
    int n = (idx >> 7) & 127;
    int k = idx & 127;
    float v = (z < RR) ? W2[((size_t)z << 14) + k * HH + n] : root2[k * HH + n];
    __nv_bfloat16 hi = __float2bfloat16(v);
    __nv_bfloat16 lo = __float2bfloat16(v - __bfloat162float(hi));
    g_Bhi[idx] = hi;
    g_Blo[idx] = lo;
}

// ================= HMMA GEMM =================
// one CTA per 128-row tile; loops z=0..8; D = Ahi*Bhi + Ahi*Blo + Alo*Bhi
// z<8 -> fp16 xr; z==8 -> fp32 g_h2 (+b2)
#define PITCH 136
#define PITCHB (PITCH * 2)
static constexpr int SM_AHI = 0;
static constexpr int SM_ALO = SM_AHI + 128 * PITCHB;
static constexpr int SM_BHI = SM_ALO + 128 * PITCHB;
static constexpr int SM_BLO = SM_BHI + 128 * PITCHB;
static constexpr int SM_TOTAL = SM_BLO + 128 * PITCHB;   // 139264 B

__global__ __launch_bounds__(256, 1) void gemm_kernel(const float* __restrict__ b2) {
    extern __shared__ char smem[];
    uint32_t sb = smem_u32(smem);
    const int tid = threadIdx.x;
    const int wid = tid >> 5, lane = tid & 31;
    const int warp_m = (wid & 3) * 32;
    const int warp_n = (wid >> 2) * 64;
    const int row0 = blockIdx.x * 128;

    // ---- stage A hi/lo (once)
    {
        uint4 zz = make_uint4(0, 0, 0, 0);
#pragma unroll
        for (int i = 0; i < 8; i++) {
            int idx = tid + i * 256;
            int row = idx >> 4, seg = idx & 15;
            int gr = row0 + row;
            bool v = gr < NN;
            uint32_t so = row * PITCHB + seg * 16;
            const uint4* Ah = reinterpret_cast<const uint4*>(g_Ahi) + (size_t)gr * 16 + seg;
            const uint4* Al = reinterpret_cast<const uint4*>(g_Alo) + (size_t)gr * 16 + seg;
            *reinterpret_cast<uint4*>(smem + SM_AHI + so) = v ? *Ah : zz;
            *reinterpret_cast<uint4*>(smem + SM_ALO + so) = v ? *Al : zz;
        }
    }

    const uint32_t a_row = (uint32_t)(warp_m + (lane & 15));
    const uint32_t a_base = a_row * PITCHB + ((lane >> 4) << 3) * 2;
    const uint32_t b_n = (uint32_t)(warp_n + (lane & 7) + ((lane >> 4) << 3));
    const uint32_t b_base = b_n * PITCHB + (((lane >> 3) & 1) << 3) * 2;

    for (int z = 0; z < NZ; z++) {
        __syncthreads();
        // ---- stage B hi/lo for this z (z-stride = 2048 uint4)
#pragma unroll
        for (int i = 0; i < 8; i++) {
            int idx = tid + i * 256;
            int row = idx >> 4, seg = idx & 15;
            uint32_t so = row * PITCHB + seg * 16;
            const uint4* Bh = reinterpret_cast<const uint4*>(g_Bhi) + (size_t)z * 2048 + row * 16 + seg;
            const uint4* Bl = reinterpret_cast<const uint4*>(g_Blo) + (size_t)z * 2048 + row * 16 + seg;
            *reinterpret_cast<uint4*>(smem + SM_BHI + so) = *Bh;
            *reinterpret_cast<uint4*>(smem + SM_BLO + so) = *Bl;
        }
        __syncthreads();

        float acc[16][4];
#pragma unroll
        for (int i = 0; i < 16; i++)
#pragma unroll
            for (int j = 0; j < 4; j++) acc[i][j] = 0.f;

#pragma unroll
        for (int k = 0; k < 8; k++) {
            const uint32_t koff = (uint32_t)(k * 32);
            uint32_t ahi[2][4], alo[2][4];
#pragma unroll
            for (int mt = 0; mt < 2; mt++) {
                uint32_t ao = a_base + (uint32_t)(mt * 16) * PITCHB + koff;
                ldsm4(ahi[mt], sb + SM_AHI + ao);
                ldsm4(alo[mt], sb + SM_ALO + ao);
            }
            uint32_t bhi[8][2], blo[8][2];
#pragma unroll
            for (int ntp = 0; ntp < 4; ntp++) {
                uint32_t bo = b_base + (uint32_t)(ntp * 16) * PITCHB + koff;
                uint32_t rh[4], rl[4];
                ldsm4(rh, sb + SM_BHI + bo);
                ldsm4(rl, sb + SM_BLO + bo);
                bhi[ntp * 2][0] = rh[0]; bhi[ntp * 2][1] = rh[1];
                bhi[ntp * 2 + 1][0] = rh[2]; bhi[ntp * 2 + 1][1] = rh[3];
                blo[ntp * 2][0] = rl[0]; blo[ntp * 2][1] = rl[1];
                blo[ntp * 2 + 1][0] = rl[2]; blo[ntp * 2 + 1][1] = rl[3];
            }
#pragma unroll
            for (int mt = 0; mt < 2; mt++)
#pragma unroll
                for (int nt = 0; nt < 8; nt++) {
                    mma_bf16(acc[mt * 8 + nt], ahi[mt], bhi[nt]);
                    mma_bf16(acc[mt * 8 + nt], ahi[mt], blo[nt]);
                    mma_bf16(acc[mt * 8 + nt], alo[mt], bhi[nt]);
                }
        }

        // ---- epilogue
        const int erow = lane >> 2;
        const int ecol0 = (lane & 3) * 2;
        if (z < RR) {
            __half* out = g_xr + (size_t)z * NN * HH;
#pragma unroll
            for (int mt = 0; mt < 2; mt++) {
                int r0 = row0 + warp_m + mt * 16 + erow;
                int r1 = r0 + 8;
                bool v0 = r0 < NN, v1 = r1 < NN;
#pragma unroll
                for (int nt = 0; nt < 8; nt++) {
                    int c = warp_n + nt * 8 + ecol0;
                    float* a4 = acc[mt * 8 + nt];
                    if (v0) {
                        __half2 o = __floats2half2_rn(a4[0], a4[1]);
                        *reinterpret_cast<__half2*>(out + (size_t)r0 * HH + c) = o;
                    }
                    if (v1) {
                        __half2 o = __floats2half2_rn(a4[2], a4[3]);
                        *reinterpret_cast<__half2*>(out + (size_t)r1 * HH + c) = o;
                    }
                }
            }
        } else {
            float* out = g_h2;
#pragma unroll
            for (int mt = 0; mt < 2; mt++) {
                int r0 = row0 + warp_m + mt * 16 + erow;
                int r1 = r0 + 8;
                bool v0 = r0 < NN, v1 = r1 < NN;
#pragma unroll
                for (int nt = 0; nt < 8; nt++) {
                    int c = warp_n + nt * 8 + ecol0;
                    float bb0 = b2[c], bb1 = b2[c + 1];
                    float* a4 = acc[mt * 8 + nt];
                    if (v0) {
                        float2 o = make_float2(a4[0] + bb0, a4[1] + bb1);
                        *reinterpret_cast<float2*>(out + (size_t)r0 * HH + c) = o;
                    }
                    if (v1) {
                        float2 o = make_float2(a4[2] + bb0, a4[3] + bb1);
                        *reinterpret_cast<float2*>(out + (size_t)r1 * HH + c) = o;
                    }
                }
            }
        }
    }
}

// layer 2 scatter: h2[dst] += w * xr_fp16[et, src]   (warp per edge, vector RED)
__global__ void scatter2_kernel(const int* __restrict__ ei, const int* __restrict__ et) {
    int warp = (blockIdx.x * blockDim.x + threadIdx.x) >> 5;
    int lane = threadIdx.x & 31;
    if (warp >= EE) return;
    int src = ei[warp];
    int dst = ei[EE + warp];
    int r = et[warp];
    float w = g_cnt[dst * RR + r];
    // each lane: 4 fp16 (8 bytes)
    const uint2* row = reinterpret_cast<const uint2*>(g_xr + ((size_t)r * NN + src) * HH);
    uint2 p = row[lane];
    __half2 h0 = *reinterpret_cast<__half2*>(&p.x);
    __half2 h1 = *reinterpret_cast<__half2*>(&p.y);
    float2 f0 = __half22float2(h0);
    float2 f1 = __half22float2(h1);
    red4(g_h2 + (size_t)dst * HH + lane * 4, w * f0.x, w * f0.y, w * f1.x, w * f1.y);
}

// out = relu(h2) @ lin_w + lin_b
__global__ void final_kernel(const float* __restrict__ lin_w, const float* __restrict__ lin_b,
                             float* __restrict__ out) {
    __shared__ float sw[HH * CC];
    __shared__ float sh[32][HH + 1];
    int tid = threadIdx.x;
    for (int i = tid; i < HH * CC; i += 256) sw[i] = lin_w[i];
    int n0 = blockIdx.x * 32;
    for (int i = tid; i < 32 * HH; i += 256) {
        int nl = i / HH, k = i % HH;
        int n = n0 + nl;
        sh[nl][k] = (n < NN) ? fmaxf(g_h2[(size_t)n * HH + k], 0.f) : 0.f;
    }
    __syncthreads();
#pragma unroll
    for (int j = 0; j < 5; j++) {
        int idx = tid + j * 256;
        int nl = idx / CC, c = idx % CC;
        float acc = lin_b[c];
#pragma unroll
        for (int k = 0; k < HH; k++) acc = fmaf(sh[nl][k], sw[k * CC + c], acc);
        int n = n0 + nl;
        if (n < NN) out[(size_t)n * CC + c] = acc;
    }
}

// ================= launch =================
extern "C" void kernel_launch(void* const* d_in, const int* in_sizes, int n_in,
                              void* d_out, int out_size) {
    const int* ei = (const int*)d_in[0];
    const int* et = (const int*)d_in[1];
    const float* W1 = (const float*)d_in[2];
    const float* root1 = (const float*)d_in[3];
    const float* b1 = (const float*)d_in[4];
    const float* W2 = (const float*)d_in[5];
    const float* root2 = (const float*)d_in[6];
    const float* b2 = (const float*)d_in[7];
    const float* lin_w = (const float*)d_in[8];
    const float* lin_b = (const float*)d_in[9];
    float* out = (float*)d_out;

    cudaFuncSetAttribute(gemm_kernel, cudaFuncAttributeMaxDynamicSharedMemorySize, SM_TOTAL);

    zero_kernel<<<2048, 256>>>();
    prepB_kernel<<<(NZ * HH * HH + 255) / 256, 256>>>(W2, root2);
    count_kernel<<<(EE + 255) / 256, 256>>>(ei, et);
    invert_kernel<<<(NN * RR + 255) / 256, 256>>>();
    scatter1_kernel<<<(EE * 32) / 256, 256>>>(ei, et, W1);
    fin1prepA_kernel<<<(NN * HH / 4 + 255) / 256, 256>>>(root1, b1);
    gemm_kernel<<<MTILES, 256, SM_TOTAL>>>(b2);
    scatter2_kernel<<<(EE * 32) / 256, 256>>>(ei, et);
    final_kernel<<<(NN + 31) / 32, 256>>>(lin_w, lin_b, out);
}

// round 8
// speedup vs baseline: 2.2116x; 1.1543x over previous
#include <cuda_runtime.h>
#include <cuda_bf16.h>
#include <cuda_fp16.h>
#include <cstdint>

#define NN 50000
#define RR 8
#define HH 128
#define CC 40
#define EE 800000
#define NZ 9           // 8 relations + root2
#define MTILES 391     // ceil(NN/128)

// ---- scratch (device globals; no allocation allowed) ----
__device__ float g_cnt[NN * RR];
__device__ float g_h[(size_t)NN * HH];                 // layer-1 fp32 accumulator
__device__ __half g_xr[(size_t)RR * NN * HH];          // 102.4 MB: xr in fp16
__device__ float g_h2[(size_t)NN * HH];
__device__ __nv_bfloat16 g_Ahi[(size_t)NN * HH];
__device__ __nv_bfloat16 g_Alo[(size_t)NN * HH];
__device__ __nv_bfloat16 g_Bhi[(size_t)NZ * HH * HH];  // transposed: [z][n][k]
__device__ __nv_bfloat16 g_Blo[(size_t)NZ * HH * HH];

// ================= PTX helpers =================
__device__ __forceinline__ uint32_t smem_u32(const void* p) {
    uint32_t a;
    asm("{ .reg .u64 t; cvta.to.shared.u64 t, %1; cvt.u32.u64 %0, t; }" : "=r"(a) : "l"(p));
    return a;
}
__device__ __forceinline__ void red4(float* p, float x, float y, float z, float w) {
    asm volatile("red.global.add.v4.f32 [%0], {%1,%2,%3,%4};"
                 :: "l"(p), "f"(x), "f"(y), "f"(z), "f"(w) : "memory");
}
__device__ __forceinline__ void ldsm4(uint32_t* r, uint32_t addr) {
    asm volatile("ldmatrix.sync.aligned.m8n8.x4.shared.b16 {%0,%1,%2,%3}, [%4];"
                 : "=r"(r[0]), "=r"(r[1]), "=r"(r[2]), "=r"(r[3]) : "r"(addr));
}
__device__ __forceinline__ void mma_bf16(float* d, const uint32_t* a, const uint32_t* b) {
    asm volatile(
        "mma.sync.aligned.m16n8k16.row.col.f32.bf16.bf16.f32 "
        "{%0,%1,%2,%3}, {%4,%5,%6,%7}, {%8,%9}, {%0,%1,%2,%3};"
        : "+f"(d[0]), "+f"(d[1]), "+f"(d[2]), "+f"(d[3])
        : "r"(a[0]), "r"(a[1]), "r"(a[2]), "r"(a[3]), "r"(b[0]), "r"(b[1]));
}
__device__ __forceinline__ void cp_async16(uint32_t saddr, const void* gaddr) {
    asm volatile("cp.async.cg.shared.global [%0], [%1], 16;" :: "r"(saddr), "l"(gaddr));
}
#define CP_COMMIT() asm volatile("cp.async.commit_group;" ::: "memory")
#define CP_WAIT(n)  asm volatile("cp.async.wait_group %0;" :: "n"(n) : "memory")

// ================= phase kernels =================
__global__ void zero_kernel() {
    size_t tid = (size_t)blockIdx.x * blockDim.x + threadIdx.x;
    size_t stride = (size_t)gridDim.x * blockDim.x;
    float4 z = make_float4(0.f, 0.f, 0.f, 0.f);
    float4* h4 = reinterpret_cast<float4*>(g_h);
    for (size_t i = tid; i < (size_t)NN * HH / 4; i += stride) h4[i] = z;
    float4* c4 = reinterpret_cast<float4*>(g_cnt);
    for (size_t i = tid; i < (size_t)NN * RR / 4; i += stride) c4[i] = z;
}

__global__ void count_kernel(const int* __restrict__ ei, const int* __restrict__ et) {
    int e = blockIdx.x * blockDim.x + threadIdx.x;
    if (e < EE) atomicAdd(&g_cnt[ei[EE + e] * RR + et[e]], 1.0f);
}

__global__ void invert_kernel() {
    int i = blockIdx.x * blockDim.x + threadIdx.x;
    if (i < NN * RR) g_cnt[i] = 1.0f / fmaxf(g_cnt[i], 1.0f);
}

// layer 1 scatter: 4 edges per warp, gathers batched for MLP=4
__global__ void scatter1_kernel(const int* __restrict__ ei, const int* __restrict__ et,
                                const float* __restrict__ W1) {
    int warp = (blockIdx.x * blockDim.x + threadIdx.x) >> 5;
    int lane = threadIdx.x & 31;
    int e0 = warp * 4;
    if (e0 >= EE) return;
    int src[4], dst[4], rel[4];
#pragma unroll
    for (int j = 0; j < 4; j++) {
        src[j] = ei[e0 + j];
        dst[j] = ei[EE + e0 + j];
        rel[j] = et[e0 + j];
    }
    float4 v[4];
#pragma unroll
    for (int j = 0; j < 4; j++)
        v[j] = __ldg(reinterpret_cast<const float4*>(W1) +
                     ((size_t)rel[j] * NN + src[j]) * (HH / 4) + lane);
    float w[4];
#pragma unroll
    for (int j = 0; j < 4; j++) w[j] = g_cnt[dst[j] * RR + rel[j]];
#pragma unroll
    for (int j = 0; j < 4; j++)
        red4(g_h + (size_t)dst[j] * HH + lane * 4,
             w[j] * v[j].x, w[j] * v[j].y, w[j] * v[j].z, w[j] * v[j].w);
}

// fused: h = relu(g_h + root1 + b1) -> bf16 hi/lo split
__global__ void fin1prepA_kernel(const float* __restrict__ root1, const float* __restrict__ b1) {
    int i = blockIdx.x * blockDim.x + threadIdx.x;
    if (i >= NN * HH / 4) return;
    float4 h = reinterpret_cast<const float4*>(g_h)[i];
    float4 r = reinterpret_cast<const float4*>(root1)[i];
    float4 b = reinterpret_cast<const float4*>(b1)[i & (HH / 4 - 1)];
    float x = fmaxf(h.x + r.x + b.x, 0.f);
    float y = fmaxf(h.y + r.y + b.y, 0.f);
    float z = fmaxf(h.z + r.z + b.z, 0.f);
    float w = fmaxf(h.w + r.w + b.w, 0.f);
    __nv_bfloat16 hx = __float2bfloat16(x), hy = __float2bfloat16(y);
    __nv_bfloat16 hz = __float2bfloat16(z), hw = __float2bfloat16(w);
    __nv_bfloat16 lx = __float2bfloat16(x - __bfloat162float(hx));
    __nv_bfloat16 ly = __float2bfloat16(y - __bfloat162float(hy));
    __nv_bfloat16 lz = __float2bfloat16(z - __bfloat162float(hz));
    __nv_bfloat16 lw = __float2bfloat16(w - __bfloat162float(hw));
    __nv_bfloat162 h0 = __halves2bfloat162(hx, hy), h1 = __halves2bfloat162(hz, hw);
    __nv_bfloat162 l0 = __halves2bfloat162(lx, ly), l1 = __halves2bfloat162(lz, lw);
    uint2 ph, pl;
    ph.x = *reinterpret_cast<uint32_t*>(&h0); ph.y = *reinterpret_cast<uint32_t*>(&h1);
    pl.x = *reinterpret_cast<uint32_t*>(&l0); pl.y = *reinterpret_cast<uint32_t*>(&l1);
    reinterpret_cast<uint2*>(g_Ahi)[i] = ph;
    reinterpret_cast<uint2*>(g_Alo)[i] = pl;
}

// W2 / root2 -> transposed bf16 hi/lo:  B[z][n][k] = W[z][k][n]
__global__ void prepB_kernel(const float* __restrict__ W2, const float* __restrict__ root2) {
    int idx = blockIdx.x * blockDim.x + threadIdx.x;
    if (idx >= NZ * HH * HH) return;
    int z = idx >> 14;
    int n = (idx >> 7) & 127;
    int k = idx & 127;
    float v = (z < RR) ? W2[((size_t)z << 14) + k * HH + n] : root2[k * HH + n];
    __nv_bfloat16 hi = __float2bfloat16(v);
    __nv_bfloat16 lo = __float2bfloat16(v - __bfloat162float(hi));
    g_Bhi[idx] = hi;
    g_Blo[idx] = lo;
}

// ================= HMMA GEMM (double-buffered B via cp.async) =================
#define PITCH 136
#define PITCHB (PITCH * 2)
#define TILEB (128 * PITCHB)            // 34816 B
static constexpr int SM_AHI = 0;
static constexpr int SM_ALO = SM_AHI + TILEB;
static constexpr int SM_B0 = SM_ALO + TILEB;             // buf0: hi then lo
static constexpr int SM_B1 = SM_B0 + 2 * TILEB;          // buf1: hi then lo
static constexpr int SM_TOTAL = SM_B1 + 2 * TILEB;       // 208896 B

__device__ __forceinline__ void stage_B_async(char* smem, int buf_base, int z, int tid) {
#pragma unroll
    for (int i = 0; i < 8; i++) {
        int idx = tid + i * 256;
        int row = idx >> 4, seg = idx & 15;
        uint32_t so = row * PITCHB + seg * 16;
        const uint4* Bh = reinterpret_cast<const uint4*>(g_Bhi) + (size_t)z * 2048 + row * 16 + seg;
        const uint4* Bl = reinterpret_cast<const uint4*>(g_Blo) + (size_t)z * 2048 + row * 16 + seg;
        cp_async16(smem_u32(smem + buf_base + so), Bh);
        cp_async16(smem_u32(smem + buf_base + TILEB + so), Bl);
    }
}

__global__ __launch_bounds__(256, 1) void gemm_kernel(const float* __restrict__ b2) {
    extern __shared__ char smem[];
    uint32_t sb = smem_u32(smem);
    const int tid = threadIdx.x;
    const int wid = tid >> 5, lane = tid & 31;
    const int warp_m = (wid & 3) * 32;
    const int warp_n = (wid >> 2) * 64;
    const int row0 = blockIdx.x * 128;

    // prologue: async-stage B[0] into buf0
    stage_B_async(smem, SM_B0, 0, tid);
    CP_COMMIT();

    // ---- stage A hi/lo (once)
    {
        uint4 zz = make_uint4(0, 0, 0, 0);
#pragma unroll
        for (int i = 0; i < 8; i++) {
            int idx = tid + i * 256;
            int row = idx >> 4, seg = idx & 15;
            int gr = row0 + row;
            bool v = gr < NN;
            uint32_t so = row * PITCHB + seg * 16;
            const uint4* Ah = reinterpret_cast<const uint4*>(g_Ahi) + (size_t)gr * 16 + seg;
            const uint4* Al = reinterpret_cast<const uint4*>(g_Alo) + (size_t)gr * 16 + seg;
            *reinterpret_cast<uint4*>(smem + SM_AHI + so) = v ? *Ah : zz;
            *reinterpret_cast<uint4*>(smem + SM_ALO + so) = v ? *Al : zz;
        }
    }

    const uint32_t a_row = (uint32_t)(warp_m + (lane & 15));
    const uint32_t a_base = a_row * PITCHB + ((lane >> 4) << 3) * 2;
    const uint32_t b_n = (uint32_t)(warp_n + (lane & 7) + ((lane >> 4) << 3));
    const uint32_t b_base = b_n * PITCHB + (((lane >> 3) & 1) << 3) * 2;

    for (int z = 0; z < NZ; z++) {
        const int cur = (z & 1) ? SM_B1 : SM_B0;
        if (z + 1 < NZ) {
            stage_B_async(smem, (z & 1) ? SM_B0 : SM_B1, z + 1, tid);
            CP_COMMIT();
            CP_WAIT(1);
        } else {
            CP_WAIT(0);
        }
        __syncthreads();

        float acc[16][4];
#pragma unroll
        for (int i = 0; i < 16; i++)
#pragma unroll
            for (int j = 0; j < 4; j++) acc[i][j] = 0.f;

#pragma unroll
        for (int k = 0; k < 8; k++) {
            const uint32_t koff = (uint32_t)(k * 32);
            uint32_t ahi[2][4], alo[2][4];
#pragma unroll
            for (int mt = 0; mt < 2; mt++) {
                uint32_t ao = a_base + (uint32_t)(mt * 16) * PITCHB + koff;
                ldsm4(ahi[mt], sb + SM_AHI + ao);
                ldsm4(alo[mt], sb + SM_ALO + ao);
            }
            uint32_t bhi[8][2], blo[8][2];
#pragma unroll
            for (int ntp = 0; ntp < 4; ntp++) {
                uint32_t bo = b_base + (uint32_t)(ntp * 16) * PITCHB + koff;
                uint32_t rh[4], rl[4];
                ldsm4(rh, sb + cur + bo);
                ldsm4(rl, sb + cur + TILEB + bo);
                bhi[ntp * 2][0] = rh[0]; bhi[ntp * 2][1] = rh[1];
                bhi[ntp * 2 + 1][0] = rh[2]; bhi[ntp * 2 + 1][1] = rh[3];
                blo[ntp * 2][0] = rl[0]; blo[ntp * 2][1] = rl[1];
                blo[ntp * 2 + 1][0] = rl[2]; blo[ntp * 2 + 1][1] = rl[3];
            }
#pragma unroll
            for (int mt = 0; mt < 2; mt++)
#pragma unroll
                for (int nt = 0; nt < 8; nt++) {
                    mma_bf16(acc[mt * 8 + nt], ahi[mt], bhi[nt]);
                    mma_bf16(acc[mt * 8 + nt], ahi[mt], blo[nt]);
                    mma_bf16(acc[mt * 8 + nt], alo[mt], bhi[nt]);
                }
        }

        // ---- epilogue
        const int erow = lane >> 2;
        const int ecol0 = (lane & 3) * 2;
        if (z < RR) {
            __half* out = g_xr + (size_t)z * NN * HH;
#pragma unroll
            for (int mt = 0; mt < 2; mt++) {
                int r0 = row0 + warp_m + mt * 16 + erow;
                int r1 = r0 + 8;
                bool v0 = r0 < NN, v1 = r1 < NN;
#pragma unroll
                for (int nt = 0; nt < 8; nt++) {
                    int c = warp_n + nt * 8 + ecol0;
                    float* a4 = acc[mt * 8 + nt];
                    if (v0) {
                        __half2 o = __floats2half2_rn(a4[0], a4[1]);
                        *reinterpret_cast<__half2*>(out + (size_t)r0 * HH + c) = o;
                    }
                    if (v1) {
                        __half2 o = __floats2half2_rn(a4[2], a4[3]);
                        *reinterpret_cast<__half2*>(out + (size_t)r1 * HH + c) = o;
                    }
                }
            }
        } else {
            float* out = g_h2;
#pragma unroll
            for (int mt = 0; mt < 2; mt++) {
                int r0 = row0 + warp_m + mt * 16 + erow;
                int r1 = r0 + 8;
                bool v0 = r0 < NN, v1 = r1 < NN;
#pragma unroll
                for (int nt = 0; nt < 8; nt++) {
                    int c = warp_n + nt * 8 + ecol0;
                    float bb0 = b2[c], bb1 = b2[c + 1];
                    float* a4 = acc[mt * 8 + nt];
                    if (v0) {
                        float2 o = make_float2(a4[0] + bb0, a4[1] + bb1);
                        *reinterpret_cast<float2*>(out + (size_t)r0 * HH + c) = o;
                    }
                    if (v1) {
                        float2 o = make_float2(a4[2] + bb0, a4[3] + bb1);
                        *reinterpret_cast<float2*>(out + (size_t)r1 * HH + c) = o;
                    }
                }
            }
        }
        __syncthreads();   // all reads of cur done before it is overwritten (iter z+1 stages z+2)
    }
}

// layer 2 scatter: 4 edges per warp, fp16 gathers batched for MLP=4
__global__ void scatter2_kernel(const int* __restrict__ ei, const int* __restrict__ et) {
    int warp = (blockIdx.x * blockDim.x + threadIdx.x) >> 5;
    int lane = threadIdx.x & 31;
    int e0 = warp * 4;
    if (e0 >= EE) return;
    int src[4], dst[4], rel[4];
#pragma unroll
    for (int j = 0; j < 4; j++) {
        src[j] = ei[e0 + j];
        dst[j] = ei[EE + e0 + j];
        rel[j] = et[e0 + j];
    }
    uint2 p[4];
#pragma unroll
    for (int j = 0; j < 4; j++)
        p[j] = __ldg(reinterpret_cast<const uint2*>(g_xr + ((size_t)rel[j] * NN + src[j]) * HH) + lane);
    float w[4];
#pragma unroll
    for (int j = 0; j < 4; j++) w[j] = g_cnt[dst[j] * RR + rel[j]];
#pragma unroll
    for (int j = 0; j < 4; j++) {
        __half2 h0 = *reinterpret_cast<__half2*>(&p[j].x);
        __half2 h1 = *reinterpret_cast<__half2*>(&p[j].y);
        float2 f0 = __half22float2(h0);
        float2 f1 = __half22float2(h1);
        red4(g_h2 + (size_t)dst[j] * HH + lane * 4,
             w[j] * f0.x, w[j] * f0.y, w[j] * f1.x, w[j] * f1.y);
    }
}

// out = relu(h2) @ lin_w + lin_b
__global__ void final_kernel(const float* __restrict__ lin_w, const float* __restrict__ lin_b,
                             float* __restrict__ out) {
    __shared__ float sw[HH * CC];
    __shared__ float sh[32][HH + 1];
    int tid = threadIdx.x;
    for (int i = tid; i < HH * CC; i += 256) sw[i] = lin_w[i];
    int n0 = blockIdx.x * 32;
    for (int i = tid; i < 32 * HH; i += 256) {
        int nl = i / HH, k = i % HH;
        int n = n0 + nl;
        sh[nl][k] = (n < NN) ? fmaxf(g_h2[(size_t)n * HH + k], 0.f) : 0.f;
    }
    __syncthreads();
#pragma unroll
    for (int j = 0; j < 5; j++) {
        int idx = tid + j * 256;
        int nl = idx / CC, c = idx % CC;
        float acc = lin_b[c];
#pragma unroll
        for (int k = 0; k < HH; k++) acc = fmaf(sh[nl][k], sw[k * CC + c], acc);
        int n = n0 + nl;
        if (n < NN) out[(size_t)n * CC + c] = acc;
    }
}

// ================= launch =================
extern "C" void kernel_launch(void* const* d_in, const int* in_sizes, int n_in,
                              void* d_out, int out_size) {
    const int* ei = (const int*)d_in[0];
    const int* et = (const int*)d_in[1];
    const float* W1 = (const float*)d_in[2];
    const float* root1 = (const float*)d_in[3];
    const float* b1 = (const float*)d_in[4];
    const float* W2 = (const float*)d_in[5];
    const float* root2 = (const float*)d_in[6];
    const float* b2 = (const float*)d_in[7];
    const float* lin_w = (const float*)d_in[8];
    const float* lin_b = (const float*)d_in[9];
    float* out = (float*)d_out;

    cudaFuncSetAttribute(gemm_kernel, cudaFuncAttributeMaxDynamicSharedMemorySize, SM_TOTAL);

    zero_kernel<<<2048, 256>>>();
    prepB_kernel<<<(NZ * HH * HH + 255) / 256, 256>>>(W2, root2);
    count_kernel<<<(EE + 255) / 256, 256>>>(ei, et);
    invert_kernel<<<(NN * RR + 255) / 256, 256>>>();
    scatter1_kernel<<<(EE / 4 + 7) / 8, 256>>>(ei, et, W1);   // 4 edges/warp, 8 warps/block
    fin1prepA_kernel<<<(NN * HH / 4 + 255) / 256, 256>>>(root1, b1);
    gemm_kernel<<<MTILES, 256, SM_TOTAL>>>(b2);
    scatter2_kernel<<<(EE / 4 + 7) / 8, 256>>>(ei, et);
    final_kernel<<<(NN + 31) / 32, 256>>>(lin_w, lin_b, out);
}

// round 10
// speedup vs baseline: 2.2737x; 1.0281x over previous
#include <cuda_runtime.h>
#include <cuda_bf16.h>
#include <cuda_fp16.h>
#include <cstdint>

#define NN 50000
#define RR 8
#define HH 128
#define CC 40
#define EE 800000
#define NZ 9           // 8 relations + root2
#define MTILES 391     // ceil(NN/128)

// ---- scratch (device globals; no allocation allowed) ----
__device__ float g_cnt[NN * RR];                       // raw counts
__device__ float g_h[(size_t)NN * HH];                 // layer-1 fp32 accumulator
__device__ __half g_xr[(size_t)RR * NN * HH];          // 102.4 MB: xr in fp16
__device__ float g_h2[(size_t)NN * HH];
__device__ __nv_bfloat16 g_Ahi[(size_t)NN * HH];
__device__ __nv_bfloat16 g_Alo[(size_t)NN * HH];
__device__ __nv_bfloat16 g_Bhi[(size_t)NZ * HH * HH];  // transposed: [z][n][k]
__device__ __nv_bfloat16 g_Blo[(size_t)NZ * HH * HH];

// ================= PTX helpers =================
__device__ __forceinline__ uint32_t smem_u32(const void* p) {
    uint32_t a;
    asm("{ .reg .u64 t; cvta.to.shared.u64 t, %1; cvt.u32.u64 %0, t; }" : "=r"(a) : "l"(p));
    return a;
}
__device__ __forceinline__ void red4(float* p, float x, float y, float z, float w) {
    asm volatile("red.global.add.v4.f32 [%0], {%1,%2,%3,%4};"
                 :: "l"(p), "f"(x), "f"(y), "f"(z), "f"(w) : "memory");
}
__device__ __forceinline__ void ldsm4(uint32_t* r, uint32_t addr) {
    asm volatile("ldmatrix.sync.aligned.m8n8.x4.shared.b16 {%0,%1,%2,%3}, [%4];"
                 : "=r"(r[0]), "=r"(r[1]), "=r"(r[2]), "=r"(r[3]) : "r"(addr));
}
__device__ __forceinline__ void mma_bf16(float* d, const uint32_t* a, const uint32_t* b) {
    asm volatile(
        "mma.sync.aligned.m16n8k16.row.col.f32.bf16.bf16.f32 "
        "{%0,%1,%2,%3}, {%4,%5,%6,%7}, {%8,%9}, {%0,%1,%2,%3};"
        : "+f"(d[0]), "+f"(d[1]), "+f"(d[2]), "+f"(d[3])
        : "r"(a[0]), "r"(a[1]), "r"(a[2]), "r"(a[3]), "r"(b[0]), "r"(b[1]));
}
__device__ __forceinline__ void cp_async16(uint32_t saddr, const void* gaddr) {
    asm volatile("cp.async.cg.shared.global [%0], [%1], 16;" :: "r"(saddr), "l"(gaddr));
}
#define CP_COMMIT() asm volatile("cp.async.commit_group;" ::: "memory")
#define CP_WAIT(n)  asm volatile("cp.async.wait_group %0;" :: "n"(n) : "memory")

// ================= phase kernels =================
__global__ void zero_kernel() {
    size_t tid = (size_t)blockIdx.x * blockDim.x + threadIdx.x;
    size_t stride = (size_t)gridDim.x * blockDim.x;
    float4 z = make_float4(0.f, 0.f, 0.f, 0.f);
    float4* h4 = reinterpret_cast<float4*>(g_h);
    for (size_t i = tid; i < (size_t)NN * HH / 4; i += stride) h4[i] = z;
    float4* c4 = reinterpret_cast<float4*>(g_cnt);
    for (size_t i = tid; i < (size_t)NN * RR / 4; i += stride) c4[i] = z;
}

__global__ void count_kernel(const int* __restrict__ ei, const int* __restrict__ et) {
    int e = blockIdx.x * blockDim.x + threadIdx.x;
    if (e < EE) atomicAdd(&g_cnt[ei[EE + e] * RR + et[e]], 1.0f);
}

// layer 1 scatter: 8 edges per warp, gathers batched for MLP=8; w computed inline
__global__ void scatter1_kernel(const int* __restrict__ ei, const int* __restrict__ et,
                                const float* __restrict__ W1) {
    int warp = (blockIdx.x * blockDim.x + threadIdx.x) >> 5;
    int lane = threadIdx.x & 31;
    int e0 = warp * 8;
    if (e0 >= EE) return;
    int src[8], dst[8], rel[8];
#pragma unroll
    for (int j = 0; j < 8; j++) {
        src[j] = ei[e0 + j];
        dst[j] = ei[EE + e0 + j];
        rel[j] = et[e0 + j];
    }
    float4 v[8];
#pragma unroll
    for (int j = 0; j < 8; j++)
        v[j] = __ldg(reinterpret_cast<const float4*>(W1) +
                     ((size_t)rel[j] * NN + src[j]) * (HH / 4) + lane);
    float w[8];
#pragma unroll
    for (int j = 0; j < 8; j++) w[j] = g_cnt[dst[j] * RR + rel[j]];
#pragma unroll
    for (int j = 0; j < 8; j++) w[j] = __frcp_rn(fmaxf(w[j], 1.0f));
#pragma unroll
    for (int j = 0; j < 8; j++)
        red4(g_h + (size_t)dst[j] * HH + lane * 4,
             w[j] * v[j].x, w[j] * v[j].y, w[j] * v[j].z, w[j] * v[j].w);
}

// fused: h = relu(g_h + root1 + b1) -> bf16 hi/lo split
__global__ void fin1prepA_kernel(const float* __restrict__ root1, const float* __restrict__ b1) {
    int i = blockIdx.x * blockDim.x + threadIdx.x;
    if (i >= NN * HH / 4) return;
    float4 h = reinterpret_cast<const float4*>(g_h)[i];
    float4 r = reinterpret_cast<const float4*>(root1)[i];
    float4 b = reinterpret_cast<const float4*>(b1)[i & (HH / 4 - 1)];
    float x = fmaxf(h.x + r.x + b.x, 0.f);
    float y = fmaxf(h.y + r.y + b.y, 0.f);
    float z = fmaxf(h.z + r.z + b.z, 0.f);
    float w = fmaxf(h.w + r.w + b.w, 0.f);
    __nv_bfloat16 hx = __float2bfloat16(x), hy = __float2bfloat16(y);
    __nv_bfloat16 hz = __float2bfloat16(z), hw = __float2bfloat16(w);
    __nv_bfloat16 lx = __float2bfloat16(x - __bfloat162float(hx));
    __nv_bfloat16 ly = __float2bfloat16(y - __bfloat162float(hy));
    __nv_bfloat16 lz = __float2bfloat16(z - __bfloat162float(hz));
    __nv_bfloat16 lw = __float2bfloat16(w - __bfloat162float(hw));
    __nv_bfloat162 h0 = __halves2bfloat162(hx, hy), h1 = __halves2bfloat162(hz, hw);
    __nv_bfloat162 l0 = __halves2bfloat162(lx, ly), l1 = __halves2bfloat162(lz, lw);
    uint2 ph, pl;
    ph.x = *reinterpret_cast<uint32_t*>(&h0); ph.y = *reinterpret_cast<uint32_t*>(&h1);
    pl.x = *reinterpret_cast<uint32_t*>(&l0); pl.y = *reinterpret_cast<uint32_t*>(&l1);
    reinterpret_cast<uint2*>(g_Ahi)[i] = ph;
    reinterpret_cast<uint2*>(g_Alo)[i] = pl;
}

// W2 / root2 -> transposed bf16 hi/lo:  B[z][n][k] = W[z][k][n]
__global__ void prepB_kernel(const float* __restrict__ W2, const float* __restrict__ root2) {
    int idx = blockIdx.x * blockDim.x + threadIdx.x;
    if (idx >= NZ * HH * HH) return;
    int z = idx >> 14;
    int n = (idx >> 7) & 127;
    int k = idx & 127;
    float v = (z < RR) ? W2[((size_t)z << 14) + k * HH + n] : root2[k * HH + n];
    __nv_bfloat16 hi = __float2bfloat16(v);
    __nv_bfloat16 lo = __float2bfloat16(v - __bfloat162float(hi));
    g_Bhi[idx] = hi;
    g_Blo[idx] = lo;
}

// ================= HMMA GEMM (double-buffered B via cp.async) =================
#define PITCH 136
#define PITCHB (PITCH * 2)
#define TILEB (128 * PITCHB)            // 34816 B
static constexpr int SM_AHI = 0;
static constexpr int SM_ALO = SM_AHI + TILEB;
static constexpr int SM_B0 = SM_ALO + TILEB;             // buf0: hi then lo
static constexpr int SM_B1 = SM_B0 + 2 * TILEB;          // buf1: hi then lo
static constexpr int SM_TOTAL = SM_B1 + 2 * TILEB;       // 208896 B

__device__ __forceinline__ void stage_B_async(char* smem, int buf_base, int z, int tid) {
#pragma unroll
    for (int i = 0; i < 8; i++) {
        int idx = tid + i * 256;
        int row = idx >> 4, seg = idx & 15;
        uint32_t so = row * PITCHB + seg * 16;
        const uint4* Bh = reinterpret_cast<const uint4*>(g_Bhi) + (size_t)z * 2048 + row * 16 + seg;
        const uint4* Bl = reinterpret_cast<const uint4*>(g_Blo) + (size_t)z * 2048 + row * 16 + seg;
        cp_async16(smem_u32(smem + buf_base + so), Bh);
        cp_async16(smem_u32(smem + buf_base + TILEB + so), Bl);
    }
}

__global__ __launch_bounds__(256, 1) void gemm_kernel(const float* __restrict__ b2) {
    extern __shared__ char smem[];
    uint32_t sb = smem_u32(smem);
    const int tid = threadIdx.x;
    const int wid = tid >> 5, lane = tid & 31;
    const int warp_m = (wid & 3) * 32;
    const int warp_n = (wid >> 2) * 64;
    const int row0 = blockIdx.x * 128;

    // prologue: async-stage B[0] into buf0
    stage_B_async(smem, SM_B0, 0, tid);
    CP_COMMIT();

    // ---- stage A hi/lo (once)
    {
        uint4 zz = make_uint4(0, 0, 0, 0);
#pragma unroll
        for (int i = 0; i < 8; i++) {
            int idx = tid + i * 256;
            int row = idx >> 4, seg = idx & 15;
            int gr = row0 + row;
            bool v = gr < NN;
            uint32_t so = row * PITCHB + seg * 16;
            const uint4* Ah = reinterpret_cast<const uint4*>(g_Ahi) + (size_t)gr * 16 + seg;
            const uint4* Al = reinterpret_cast<const uint4*>(g_Alo) + (size_t)gr * 16 + seg;
            *reinterpret_cast<uint4*>(smem + SM_AHI + so) = v ? *Ah : zz;
            *reinterpret_cast<uint4*>(smem + SM_ALO + so) = v ? *Al : zz;
        }
    }

    const uint32_t a_row = (uint32_t)(warp_m + (lane & 15));
    const uint32_t a_base = a_row * PITCHB + ((lane >> 4) << 3) * 2;
    const uint32_t b_n = (uint32_t)(warp_n + (lane & 7) + ((lane >> 4) << 3));
    const uint32_t b_base = b_n * PITCHB + (((lane >> 3) & 1) << 3) * 2;

    for (int z = 0; z < NZ; z++) {
        const int cur = (z & 1) ? SM_B1 : SM_B0;
        if (z + 1 < NZ) {
            stage_B_async(smem, (z & 1) ? SM_B0 : SM_B1, z + 1, tid);
            CP_COMMIT();
            CP_WAIT(1);
        } else {
            CP_WAIT(0);
        }
        __syncthreads();

        float acc[16][4];
#pragma unroll
        for (int i = 0; i < 16; i++)
#pragma unroll
            for (int j = 0; j < 4; j++) acc[i][j] = 0.f;

#pragma unroll
        for (int k = 0; k < 8; k++) {
            const uint32_t koff = (uint32_t)(k * 32);
            uint32_t ahi[2][4], alo[2][4];
#pragma unroll
            for (int mt = 0; mt < 2; mt++) {
                uint32_t ao = a_base + (uint32_t)(mt * 16) * PITCHB + koff;
                ldsm4(ahi[mt], sb + SM_AHI + ao);
                ldsm4(alo[mt], sb + SM_ALO + ao);
            }
            uint32_t bhi[8][2], blo[8][2];
#pragma unroll
            for (int ntp = 0; ntp < 4; ntp++) {
                uint32_t bo = b_base + (uint32_t)(ntp * 16) * PITCHB + koff;
                uint32_t rh[4], rl[4];
                ldsm4(rh, sb + cur + bo);
                ldsm4(rl, sb + cur + TILEB + bo);
                bhi[ntp * 2][0] = rh[0]; bhi[ntp * 2][1] = rh[1];
                bhi[ntp * 2 + 1][0] = rh[2]; bhi[ntp * 2 + 1][1] = rh[3];
                blo[ntp * 2][0] = rl[0]; blo[ntp * 2][1] = rl[1];
                blo[ntp * 2 + 1][0] = rl[2]; blo[ntp * 2 + 1][1] = rl[3];
            }
#pragma unroll
            for (int mt = 0; mt < 2; mt++)
#pragma unroll
                for (int nt = 0; nt < 8; nt++) {
                    mma_bf16(acc[mt * 8 + nt], ahi[mt], bhi[nt]);
                    mma_bf16(acc[mt * 8 + nt], ahi[mt], blo[nt]);
                    mma_bf16(acc[mt * 8 + nt], alo[mt], bhi[nt]);
                }
        }

        // ---- epilogue
        const int erow = lane >> 2;
        const int ecol0 = (lane & 3) * 2;
        if (z < RR) {
            __half* out = g_xr + (size_t)z * NN * HH;
#pragma unroll
            for (int mt = 0; mt < 2; mt++) {
                int r0 = row0 + warp_m + mt * 16 + erow;
                int r1 = r0 + 8;
                bool v0 = r0 < NN, v1 = r1 < NN;
#pragma unroll
                for (int nt = 0; nt < 8; nt++) {
                    int c = warp_n + nt * 8 + ecol0;
                    float* a4 = acc[mt * 8 + nt];
                    if (v0) {
                        __half2 o = __floats2half2_rn(a4[0], a4[1]);
                        *reinterpret_cast<__half2*>(out + (size_t)r0 * HH + c) = o;
                    }
                    if (v1) {
                        __half2 o = __floats2half2_rn(a4[2], a4[3]);
                        *reinterpret_cast<__half2*>(out + (size_t)r1 * HH + c) = o;
                    }
                }
            }
        } else {
            float* out = g_h2;
#pragma unroll
            for (int mt = 0; mt < 2; mt++) {
                int r0 = row0 + warp_m + mt * 16 + erow;
                int r1 = r0 + 8;
                bool v0 = r0 < NN, v1 = r1 < NN;
#pragma unroll
                for (int nt = 0; nt < 8; nt++) {
                    int c = warp_n + nt * 8 + ecol0;
                    float bb0 = b2[c], bb1 = b2[c + 1];
                    float* a4 = acc[mt * 8 + nt];
                    if (v0) {
                        float2 o = make_float2(a4[0] + bb0, a4[1] + bb1);
                        *reinterpret_cast<float2*>(out + (size_t)r0 * HH + c) = o;
                    }
                    if (v1) {
                        float2 o = make_float2(a4[2] + bb0, a4[3] + bb1);
                        *reinterpret_cast<float2*>(out + (size_t)r1 * HH + c) = o;
                    }
                }
            }
        }
        __syncthreads();   // all reads of cur done before it is overwritten
    }
}

// layer 2 scatter: 8 edges per warp, fp16 gathers batched for MLP=8; w inline
__global__ void scatter2_kernel(const int* __restrict__ ei, const int* __restrict__ et) {
    int warp = (blockIdx.x * blockDim.x + threadIdx.x) >> 5;
    int lane = threadIdx.x & 31;
    int e0 = warp * 8;
    if (e0 >= EE) return;
    int src[8], dst[8], rel[8];
#pragma unroll
    for (int j = 0; j < 8; j++) {
        src[j] = ei[e0 + j];
        dst[j] = ei[EE + e0 + j];
        rel[j] = et[e0 + j];
    }
    uint2 p[8];
#pragma unroll
    for (int j = 0; j < 8; j++)
        p[j] = __ldg(reinterpret_cast<const uint2*>(g_xr + ((size_t)rel[j] * NN + src[j]) * HH) + lane);
    float w[8];
#pragma unroll
    for (int j = 0; j < 8; j++) w[j] = g_cnt[dst[j] * RR + rel[j]];
#pragma unroll
    for (int j = 0; j < 8; j++) w[j] = __frcp_rn(fmaxf(w[j], 1.0f));
#pragma unroll
    for (int j = 0; j < 8; j++) {
        __half2 h0 = *reinterpret_cast<__half2*>(&p[j].x);
        __half2 h1 = *reinterpret_cast<__half2*>(&p[j].y);
        float2 f0 = __half22float2(h0);
        float2 f1 = __half22float2(h1);
        red4(g_h2 + (size_t)dst[j] * HH + lane * 4,
             w[j] * f0.x, w[j] * f0.y, w[j] * f1.x, w[j] * f1.y);
    }
}

// out = relu(h2) @ lin_w + lin_b
__global__ void final_kernel(const float* __restrict__ lin_w, const float* __restrict__ lin_b,
                             float* __restrict__ out) {
    __shared__ float sw[HH * CC];
    __shared__ float sh[32][HH + 1];
    int tid = threadIdx.x;
    for (int i = tid; i < HH * CC; i += 256) sw[i] = lin_w[i];
    int n0 = blockIdx.x * 32;
    for (int i = tid; i < 32 * HH; i += 256) {
        int nl = i / HH, k = i % HH;
        int n = n0 + nl;
        sh[nl][k] = (n < NN) ? fmaxf(g_h2[(size_t)n * HH + k], 0.f) : 0.f;
    }
    __syncthreads();
#pragma unroll
    for (int j = 0; j < 5; j++) {
        int idx = tid + j * 256;
        int nl = idx / CC, c = idx % CC;
        float acc = lin_b[c];
#pragma unroll
        for (int k = 0; k < HH; k++) acc = fmaf(sh[nl][k], sw[k * CC + c], acc);
        int n = n0 + nl;
        if (n < NN) out[(size_t)n * CC + c] = acc;
    }
}

// ================= launch =================
extern "C" void kernel_launch(void* const* d_in, const int* in_sizes, int n_in,
                              void* d_out, int out_size) {
    const int* ei = (const int*)d_in[0];
    const int* et = (const int*)d_in[1];
    const float* W1 = (const float*)d_in[2];
    const float* root1 = (const float*)d_in[3];
    const float* b1 = (const float*)d_in[4];
    const float* W2 = (const float*)d_in[5];
    const float* root2 = (const float*)d_in[6];
    const float* b2 = (const float*)d_in[7];
    const float* lin_w = (const float*)d_in[8];
    const float* lin_b = (const float*)d_in[9];
    float* out = (float*)d_out;

    cudaFuncSetAttribute(gemm_kernel, cudaFuncAttributeMaxDynamicSharedMemorySize, SM_TOTAL);

    zero_kernel<<<2048, 256>>>();
    prepB_kernel<<<(NZ * HH * HH + 255) / 256, 256>>>(W2, root2);
    count_kernel<<<(EE + 255) / 256, 256>>>(ei, et);
    scatter1_kernel<<<(EE / 8 + 7) / 8, 256>>>(ei, et, W1);   // 8 edges/warp, 8 warps/block
    fin1prepA_kernel<<<(NN * HH / 4 + 255) / 256, 256>>>(root1, b1);
    gemm_kernel<<<MTILES, 256, SM_TOTAL>>>(b2);
    scatter2_kernel<<<(EE / 8 + 7) / 8, 256>>>(ei, et);
    final_kernel<<<(NN + 31) / 32, 256>>>(lin_w, lin_b, out);
}

// round 11
// speedup vs baseline: 2.3191x; 1.0200x over previous
#include <cuda_runtime.h>
#include <cuda_bf16.h>
#include <cuda_fp16.h>
#include <cstdint>

#define NN 50000
#define RR 8
#define HH 128
#define CC 40
#define EE 800000
#define NZ 9           // 8 relations + root2
#define MTILES 391     // ceil(NN/128)

// ---- scratch (device globals; no allocation allowed) ----
__device__ float g_cnt[NN * RR];                       // raw counts
__device__ int2 g_eidx[EE];                            // packed {src, dst*8+rel}
__device__ float g_h[(size_t)NN * HH];                 // layer-1 fp32 accumulator
__device__ __half g_xr[(size_t)RR * NN * HH];          // 102.4 MB: xr in fp16
__device__ float g_h2[(size_t)NN * HH];
__device__ __nv_bfloat16 g_Ahi[(size_t)NN * HH];
__device__ __nv_bfloat16 g_Alo[(size_t)NN * HH];
__device__ __nv_bfloat16 g_Bhi[(size_t)NZ * HH * HH];  // transposed: [z][n][k]
__device__ __nv_bfloat16 g_Blo[(size_t)NZ * HH * HH];

// ================= PTX helpers =================
__device__ __forceinline__ uint32_t smem_u32(const void* p) {
    uint32_t a;
    asm("{ .reg .u64 t; cvta.to.shared.u64 t, %1; cvt.u32.u64 %0, t; }" : "=r"(a) : "l"(p));
    return a;
}
__device__ __forceinline__ void red4(float* p, float x, float y, float z, float w) {
    asm volatile("red.global.add.v4.f32 [%0], {%1,%2,%3,%4};"
                 :: "l"(p), "f"(x), "f"(y), "f"(z), "f"(w) : "memory");
}
__device__ __forceinline__ void ldsm4(uint32_t* r, uint32_t addr) {
    asm volatile("ldmatrix.sync.aligned.m8n8.x4.shared.b16 {%0,%1,%2,%3}, [%4];"
                 : "=r"(r[0]), "=r"(r[1]), "=r"(r[2]), "=r"(r[3]) : "r"(addr));
}
__device__ __forceinline__ void mma_bf16(float* d, const uint32_t* a, const uint32_t* b) {
    asm volatile(
        "mma.sync.aligned.m16n8k16.row.col.f32.bf16.bf16.f32 "
        "{%0,%1,%2,%3}, {%4,%5,%6,%7}, {%8,%9}, {%0,%1,%2,%3};"
        : "+f"(d[0]), "+f"(d[1]), "+f"(d[2]), "+f"(d[3])
        : "r"(a[0]), "r"(a[1]), "r"(a[2]), "r"(a[3]), "r"(b[0]), "r"(b[1]));
}
__device__ __forceinline__ void cp_async16(uint32_t saddr, const void* gaddr) {
    asm volatile("cp.async.cg.shared.global [%0], [%1], 16;" :: "r"(saddr), "l"(gaddr));
}
__device__ __forceinline__ void cp_async8(uint32_t saddr, const void* gaddr) {
    asm volatile("cp.async.ca.shared.global [%0], [%1], 8;" :: "r"(saddr), "l"(gaddr));
}
#define CP_COMMIT() asm volatile("cp.async.commit_group;" ::: "memory")
#define CP_WAIT(n)  asm volatile("cp.async.wait_group %0;" :: "n"(n) : "memory")

// ================= phase kernels =================
__global__ void zero_kernel() {
    size_t tid = (size_t)blockIdx.x * blockDim.x + threadIdx.x;
    size_t stride = (size_t)gridDim.x * blockDim.x;
    float4 z = make_float4(0.f, 0.f, 0.f, 0.f);
    float4* h4 = reinterpret_cast<float4*>(g_h);
    for (size_t i = tid; i < (size_t)NN * HH / 4; i += stride) h4[i] = z;
    float4* c4 = reinterpret_cast<float4*>(g_cnt);
    for (size_t i = tid; i < (size_t)NN * RR / 4; i += stride) c4[i] = z;
}

// counts + packed edge index
__global__ void count_kernel(const int* __restrict__ ei, const int* __restrict__ et) {
    int e = blockIdx.x * blockDim.x + threadIdx.x;
    if (e < EE) {
        int src = ei[e];
        int dst = ei[EE + e];
        int r = et[e];
        int seg = dst * RR + r;
        g_eidx[e] = make_int2(src, seg);
        atomicAdd(&g_cnt[seg], 1.0f);
    }
}

// layer 1 scatter: cp.async-staged, 16 edges per warp (one shot), MLP=16, low regs
__global__ __launch_bounds__(256) void scatter1_kernel(const float* __restrict__ W1) {
    extern __shared__ char smem[];
    const int wid = threadIdx.x >> 5, lane = threadIdx.x & 31;
    char* buf = smem + wid * (16 * 512);
    const int e0 = (blockIdx.x * 8 + wid) * 16;

    int2 ev = g_eidx[e0 + (lane & 15)];
    float cw = (lane < 16) ? g_cnt[ev.y] : 1.0f;
    float winv = __frcp_rn(fmaxf(cw, 1.0f));

#pragma unroll
    for (int j = 0; j < 16; j++) {
        int srcj = __shfl_sync(0xffffffffu, ev.x, j);
        int segj = __shfl_sync(0xffffffffu, ev.y, j);
        const char* g = reinterpret_cast<const char*>(W1) +
                        ((size_t)(segj & 7) * NN + srcj) * (HH * 4) + lane * 16;
        cp_async16(smem_u32(buf + j * 512 + lane * 16), g);
    }
    CP_COMMIT();
    CP_WAIT(0);

#pragma unroll
    for (int j = 0; j < 16; j++) {
        int segj = __shfl_sync(0xffffffffu, ev.y, j);
        float wj = __shfl_sync(0xffffffffu, winv, j);
        float4 v = *reinterpret_cast<float4*>(buf + j * 512 + lane * 16);
        red4(g_h + (size_t)(segj >> 3) * HH + lane * 4,
             wj * v.x, wj * v.y, wj * v.z, wj * v.w);
    }
}

// fused: h = relu(g_h + root1 + b1) -> bf16 hi/lo split
__global__ void fin1prepA_kernel(const float* __restrict__ root1, const float* __restrict__ b1) {
    int i = blockIdx.x * blockDim.x + threadIdx.x;
    if (i >= NN * HH / 4) return;
    float4 h = reinterpret_cast<const float4*>(g_h)[i];
    float4 r = reinterpret_cast<const float4*>(root1)[i];
    float4 b = reinterpret_cast<const float4*>(b1)[i & (HH / 4 - 1)];
    float x = fmaxf(h.x + r.x + b.x, 0.f);
    float y = fmaxf(h.y + r.y + b.y, 0.f);
    float z = fmaxf(h.z + r.z + b.z, 0.f);
    float w = fmaxf(h.w + r.w + b.w, 0.f);
    __nv_bfloat16 hx = __float2bfloat16(x), hy = __float2bfloat16(y);
    __nv_bfloat16 hz = __float2bfloat16(z), hw = __float2bfloat16(w);
    __nv_bfloat16 lx = __float2bfloat16(x - __bfloat162float(hx));
    __nv_bfloat16 ly = __float2bfloat16(y - __bfloat162float(hy));
    __nv_bfloat16 lz = __float2bfloat16(z - __bfloat162float(hz));
    __nv_bfloat16 lw = __float2bfloat16(w - __bfloat162float(hw));
    __nv_bfloat162 h0 = __halves2bfloat162(hx, hy), h1 = __halves2bfloat162(hz, hw);
    __nv_bfloat162 l0 = __halves2bfloat162(lx, ly), l1 = __halves2bfloat162(lz, lw);
    uint2 ph, pl;
    ph.x = *reinterpret_cast<uint32_t*>(&h0); ph.y = *reinterpret_cast<uint32_t*>(&h1);
    pl.x = *reinterpret_cast<uint32_t*>(&l0); pl.y = *reinterpret_cast<uint32_t*>(&l1);
    reinterpret_cast<uint2*>(g_Ahi)[i] = ph;
    reinterpret_cast<uint2*>(g_Alo)[i] = pl;
}

// W2 / root2 -> transposed bf16 hi/lo:  B[z][n][k] = W[z][k][n]
__global__ void prepB_kernel(const float* __restrict__ W2, const float* __restrict__ root2) {
    int idx = blockIdx.x * blockDim.x + threadIdx.x;
    if (idx >= NZ * HH * HH) return;
    int z = idx >> 14;
    int n = (idx >> 7) & 127;
    int k = idx & 127;
    float v = (z < RR) ? W2[((size_t)z << 14) + k * HH + n] : root2[k * HH + n];
    __nv_bfloat16 hi = __float2bfloat16(v);
    __nv_bfloat16 lo = __float2bfloat16(v - __bfloat162float(hi));
    g_Bhi[idx] = hi;
    g_Blo[idx] = lo;
}

// ================= HMMA GEMM (double-buffered B via cp.async) =================
#define PITCH 136
#define PITCHB (PITCH * 2)
#define TILEB (128 * PITCHB)            // 34816 B
static constexpr int SM_AHI = 0;
static constexpr int SM_ALO = SM_AHI + TILEB;
static constexpr int SM_B0 = SM_ALO + TILEB;             // buf0: hi then lo
static constexpr int SM_B1 = SM_B0 + 2 * TILEB;          // buf1: hi then lo
static constexpr int SM_TOTAL = SM_B1 + 2 * TILEB;       // 208896 B

__device__ __forceinline__ void stage_B_async(char* smem, int buf_base, int z, int tid) {
#pragma unroll
    for (int i = 0; i < 8; i++) {
        int idx = tid + i * 256;
        int row = idx >> 4, seg = idx & 15;
        uint32_t so = row * PITCHB + seg * 16;
        const uint4* Bh = reinterpret_cast<const uint4*>(g_Bhi) + (size_t)z * 2048 + row * 16 + seg;
        const uint4* Bl = reinterpret_cast<const uint4*>(g_Blo) + (size_t)z * 2048 + row * 16 + seg;
        cp_async16(smem_u32(smem + buf_base + so), Bh);
        cp_async16(smem_u32(smem + buf_base + TILEB + so), Bl);
    }
}

__global__ __launch_bounds__(256, 1) void gemm_kernel(const float* __restrict__ b2) {
    extern __shared__ char smem[];
    uint32_t sb = smem_u32(smem);
    const int tid = threadIdx.x;
    const int wid = tid >> 5, lane = tid & 31;
    const int warp_m = (wid & 3) * 32;
    const int warp_n = (wid >> 2) * 64;
    const int row0 = blockIdx.x * 128;

    // prologue: async-stage B[0] into buf0
    stage_B_async(smem, SM_B0, 0, tid);
    CP_COMMIT();

    // ---- stage A hi/lo (once)
    {
        uint4 zz = make_uint4(0, 0, 0, 0);
#pragma unroll
        for (int i = 0; i < 8; i++) {
            int idx = tid + i * 256;
            int row = idx >> 4, seg = idx & 15;
            int gr = row0 + row;
            bool v = gr < NN;
            uint32_t so = row * PITCHB + seg * 16;
            const uint4* Ah = reinterpret_cast<const uint4*>(g_Ahi) + (size_t)gr * 16 + seg;
            const uint4* Al = reinterpret_cast<const uint4*>(g_Alo) + (size_t)gr * 16 + seg;
            *reinterpret_cast<uint4*>(smem + SM_AHI + so) = v ? *Ah : zz;
            *reinterpret_cast<uint4*>(smem + SM_ALO + so) = v ? *Al : zz;
        }
    }

    const uint32_t a_row = (uint32_t)(warp_m + (lane & 15));
    const uint32_t a_base = a_row * PITCHB + ((lane >> 4) << 3) * 2;
    const uint32_t b_n = (uint32_t)(warp_n + (lane & 7) + ((lane >> 4) << 3));
    const uint32_t b_base = b_n * PITCHB + (((lane >> 3) & 1) << 3) * 2;

    for (int z = 0; z < NZ; z++) {
        const int cur = (z & 1) ? SM_B1 : SM_B0;
        if (z + 1 < NZ) {
            stage_B_async(smem, (z & 1) ? SM_B0 : SM_B1, z + 1, tid);
            CP_COMMIT();
            CP_WAIT(1);
        } else {
            CP_WAIT(0);
        }
        __syncthreads();

        float acc[16][4];
#pragma unroll
        for (int i = 0; i < 16; i++)
#pragma unroll
            for (int j = 0; j < 4; j++) acc[i][j] = 0.f;

#pragma unroll
        for (int k = 0; k < 8; k++) {
            const uint32_t koff = (uint32_t)(k * 32);
            uint32_t ahi[2][4], alo[2][4];
#pragma unroll
            for (int mt = 0; mt < 2; mt++) {
                uint32_t ao = a_base + (uint32_t)(mt * 16) * PITCHB + koff;
                ldsm4(ahi[mt], sb + SM_AHI + ao);
                ldsm4(alo[mt], sb + SM_ALO + ao);
            }
            uint32_t bhi[8][2], blo[8][2];
#pragma unroll
            for (int ntp = 0; ntp < 4; ntp++) {
                uint32_t bo = b_base + (uint32_t)(ntp * 16) * PITCHB + koff;
                uint32_t rh[4], rl[4];
                ldsm4(rh, sb + cur + bo);
                ldsm4(rl, sb + cur + TILEB + bo);
                bhi[ntp * 2][0] = rh[0]; bhi[ntp * 2][1] = rh[1];
                bhi[ntp * 2 + 1][0] = rh[2]; bhi[ntp * 2 + 1][1] = rh[3];
                blo[ntp * 2][0] = rl[0]; blo[ntp * 2][1] = rl[1];
                blo[ntp * 2 + 1][0] = rl[2]; blo[ntp * 2 + 1][1] = rl[3];
            }
#pragma unroll
            for (int mt = 0; mt < 2; mt++)
#pragma unroll
                for (int nt = 0; nt < 8; nt++) {
                    mma_bf16(acc[mt * 8 + nt], ahi[mt], bhi[nt]);
                    mma_bf16(acc[mt * 8 + nt], ahi[mt], blo[nt]);
                    mma_bf16(acc[mt * 8 + nt], alo[mt], bhi[nt]);
                }
        }

        // ---- epilogue
        const int erow = lane >> 2;
        const int ecol0 = (lane & 3) * 2;
        if (z < RR) {
            __half* out = g_xr + (size_t)z * NN * HH;
#pragma unroll
            for (int mt = 0; mt < 2; mt++) {
                int r0 = row0 + warp_m + mt * 16 + erow;
                int r1 = r0 + 8;
                bool v0 = r0 < NN, v1 = r1 < NN;
#pragma unroll
                for (int nt = 0; nt < 8; nt++) {
                    int c = warp_n + nt * 8 + ecol0;
                    float* a4 = acc[mt * 8 + nt];
                    if (v0) {
                        __half2 o = __floats2half2_rn(a4[0], a4[1]);
                        *reinterpret_cast<__half2*>(out + (size_t)r0 * HH + c) = o;
                    }
                    if (v1) {
                        __half2 o = __floats2half2_rn(a4[2], a4[3]);
                        *reinterpret_cast<__half2*>(out + (size_t)r1 * HH + c) = o;
                    }
                }
            }
        } else {
            float* out = g_h2;
#pragma unroll
            for (int mt = 0; mt < 2; mt++) {
                int r0 = row0 + warp_m + mt * 16 + erow;
                int r1 = r0 + 8;
                bool v0 = r0 < NN, v1 = r1 < NN;
#pragma unroll
                for (int nt = 0; nt < 8; nt++) {
                    int c = warp_n + nt * 8 + ecol0;
                    float bb0 = b2[c], bb1 = b2[c + 1];
                    float* a4 = acc[mt * 8 + nt];
                    if (v0) {
                        float2 o = make_float2(a4[0] + bb0, a4[1] + bb1);
                        *reinterpret_cast<float2*>(out + (size_t)r0 * HH + c) = o;
                    }
                    if (v1) {
                        float2 o = make_float2(a4[2] + bb0, a4[3] + bb1);
                        *reinterpret_cast<float2*>(out + (size_t)r1 * HH + c) = o;
                    }
                }
            }
        }
        __syncthreads();   // all reads of cur done before it is overwritten
    }
}

// layer 2 scatter: cp.async-staged fp16 rows, 16 edges per warp
__global__ __launch_bounds__(256) void scatter2_kernel() {
    extern __shared__ char smem[];
    const int wid = threadIdx.x >> 5, lane = threadIdx.x & 31;
    char* buf = smem + wid * (16 * 256);
    const int e0 = (blockIdx.x * 8 + wid) * 16;

    int2 ev = g_eidx[e0 + (lane & 15)];
    float cw = (lane < 16) ? g_cnt[ev.y] : 1.0f;
    float winv = __frcp_rn(fmaxf(cw, 1.0f));

#pragma unroll
    for (int j = 0; j < 16; j++) {
        int srcj = __shfl_sync(0xffffffffu, ev.x, j);
        int segj = __shfl_sync(0xffffffffu, ev.y, j);
        const char* g = reinterpret_cast<const char*>(g_xr) +
                        ((size_t)(segj & 7) * NN + srcj) * (HH * 2) + lane * 8;
        cp_async8(smem_u32(buf + j * 256 + lane * 8), g);
    }
    CP_COMMIT();
    CP_WAIT(0);

#pragma unroll
    for (int j = 0; j < 16; j++) {
        int segj = __shfl_sync(0xffffffffu, ev.y, j);
        float wj = __shfl_sync(0xffffffffu, winv, j);
        uint2 p = *reinterpret_cast<uint2*>(buf + j * 256 + lane * 8);
        __half2 h0 = *reinterpret_cast<__half2*>(&p.x);
        __half2 h1 = *reinterpret_cast<__half2*>(&p.y);
        float2 f0 = __half22float2(h0);
        float2 f1 = __half22float2(h1);
        red4(g_h2 + (size_t)(segj >> 3) * HH + lane * 4,
             wj * f0.x, wj * f0.y, wj * f1.x, wj * f1.y);
    }
}

// out = relu(h2) @ lin_w + lin_b
__global__ void final_kernel(const float* __restrict__ lin_w, const float* __restrict__ lin_b,
                             float* __restrict__ out) {
    __shared__ float sw[HH * CC];
    __shared__ float sh[32][HH + 1];
    int tid = threadIdx.x;
    for (int i = tid; i < HH * CC; i += 256) sw[i] = lin_w[i];
    int n0 = blockIdx.x * 32;
    for (int i = tid; i < 32 * HH; i += 256) {
        int nl = i / HH, k = i % HH;
        int n = n0 + nl;
        sh[nl][k] = (n < NN) ? fmaxf(g_h2[(size_t)n * HH + k], 0.f) : 0.f;
    }
    __syncthreads();
#pragma unroll
    for (int j = 0; j < 5; j++) {
        int idx = tid + j * 256;
        int nl = idx / CC, c = idx % CC;
        float acc = lin_b[c];
#pragma unroll
        for (int k = 0; k < HH; k++) acc = fmaf(sh[nl][k], sw[k * CC + c], acc);
        int n = n0 + nl;
        if (n < NN) out[(size_t)n * CC + c] = acc;
    }
}

// ================= launch =================
extern "C" void kernel_launch(void* const* d_in, const int* in_sizes, int n_in,
                              void* d_out, int out_size) {
    const int* ei = (const int*)d_in[0];
    const int* et = (const int*)d_in[1];
    const float* W1 = (const float*)d_in[2];
    const float* root1 = (const float*)d_in[3];
    const float* b1 = (const float*)d_in[4];
    const float* W2 = (const float*)d_in[5];
    const float* root2 = (const float*)d_in[6];
    const float* b2 = (const float*)d_in[7];
    const float* lin_w = (const float*)d_in[8];
    const float* lin_b = (const float*)d_in[9];
    float* out = (float*)d_out;

    cudaFuncSetAttribute(gemm_kernel, cudaFuncAttributeMaxDynamicSharedMemorySize, SM_TOTAL);
    cudaFuncSetAttribute(scatter1_kernel, cudaFuncAttributeMaxDynamicSharedMemorySize, 65536);

    zero_kernel<<<2048, 256>>>();
    prepB_kernel<<<(NZ * HH * HH + 255) / 256, 256>>>(W2, root2);
    count_kernel<<<(EE + 255) / 256, 256>>>(ei, et);
    scatter1_kernel<<<EE / 128, 256, 65536>>>(W1);     // 16 edges/warp, 8 warps/block
    fin1prepA_kernel<<<(NN * HH / 4 + 255) / 256, 256>>>(root1, b1);
    gemm_kernel<<<MTILES, 256, SM_TOTAL>>>(b2);
    scatter2_kernel<<<EE / 128, 256, 32768>>>();       // 16 edges/warp, 8 warps/block
    final_kernel<<<(NN + 31) / 32, 256>>>(lin_w, lin_b, out);
}